// round 8
// baseline (speedup 1.0000x reference)
#include <cuda_runtime.h>
#include <cstdint>
#include <cstddef>

// Problem dims
#define Bc 256
#define Tc 128
#define Hc 1024
#define Vc 64
#define Lc 457
#define ML 64

typedef unsigned long long ull;

// ---------------- device scratch (no allocs allowed) ----------------
__device__ float g_U0[(size_t)Bc * Tc * Hc];   // x @ enc_Wih0^T + b0
__device__ float g_h0[2][Bc * Hc];
__device__ float g_h1[2][Bc * Hc];
__device__ float g_V [2][Bc * Hc];             // h0_t @ eWih1^T + b1
__device__ float g_d0[2][Bc * Hc];
__device__ float g_d1[2][Bc * Hc];
__device__ float g_P0[Bc * Hc];                // d0_{s-1} @ dWhh0^T (pre-rotated)
__device__ float g_P1[Bc * Hc];                // d1_{s-1} @ dWhh1^T
__device__ float g_zero[Bc * Hc];
__device__ int   g_tok[Bc];

// ---------------- packed fp32 helpers (sm_103a f32x2) ----------------
__device__ __forceinline__ void ffma2(ull& d, ull a, ull b) {
    asm("fma.rn.f32x2 %0, %1, %2, %0;" : "+l"(d) : "l"(a), "l"(b));
}
__device__ __forceinline__ void unpk(ull v, float& lo, float& hi) {
    unsigned int a, b;
    asm("mov.b64 {%0, %1}, %2;" : "=r"(a), "=r"(b) : "l"(v));
    lo = __uint_as_float(a);
    hi = __uint_as_float(b);
}

// ---------------- GEMM job descriptor (single source) ----------------
struct GemmJob {
    const float* A; long lda; const float* W;  // C = act(A @ W^T + bias + addmat)
    int K;
    const int* gather;                          // optional row gather on A
    const float* bias; const float* addmat; long ldadd;
    float* C; long ldc; int act; int valid;
};

// ---------------- tile loaders (BR rows x 16 k-cols) ----------------
template<int NT, int BR>
__device__ __forceinline__ void load_tile(
    const float* __restrict__ A, long lda, const int* __restrict__ gather,
    int r_base, int K, int k0, int tid, float (&r)[BR * 4 / NT][4])
{
    constexpr int NC = BR * 4 / NT;
#pragma unroll
    for (int i = 0; i < NC; i++) {
        int cid = tid + i * NT;
        int row = cid >> 2, kq = cid & 3;
        int kk = k0 + kq * 4;
        long arow = gather ? (long)__ldg(&gather[r_base + row]) : (long)(r_base + row);
        const float* p = A + arow * lda + kk;
        if (kk + 3 < K && ((((uintptr_t)p) & 15u) == 0)) {
            float4 v = *(const float4*)p;
            r[i][0] = v.x; r[i][1] = v.y; r[i][2] = v.z; r[i][3] = v.w;
        } else {
#pragma unroll
            for (int j = 0; j < 4; j++)
                r[i][j] = (kk + j < K) ? __ldg(p + j) : 0.0f;
        }
    }
}

// A stored VALUE-DUPLICATED: As2[k][2*row] = As2[k][2*row+1] = v
// (so the mainloop reads packed f32x2 A operands with zero MOVs)
template<int NT, int BR>
__device__ __forceinline__ void store_a_dup(
    float (&S)[16][2 * BR], int tid, const float (&r)[BR * 4 / NT][4])
{
    constexpr int NC = BR * 4 / NT;
#pragma unroll
    for (int i = 0; i < NC; i++) {
        int cid = tid + i * NT;
        int row = cid >> 2, kq = cid & 3;
#pragma unroll
        for (int j = 0; j < 4; j++) {
            float v = r[i][j];
            *(float2*)&S[kq * 4 + j][2 * row] = make_float2(v, v);
        }
    }
}

// W stored naturally: Ws[k][col]; adjacent col pairs read as packed f32x2
template<int NT, int BR>
__device__ __forceinline__ void store_w(
    float (&S)[16][BR], int tid, const float (&r)[BR * 4 / NT][4])
{
    constexpr int NC = BR * 4 / NT;
#pragma unroll
    for (int i = 0; i < NC; i++) {
        int cid = tid + i * NT;
        int row = cid >> 2, kq = cid & 3;
#pragma unroll
        for (int j = 0; j < 4; j++)
            S[kq * 4 + j][row] = r[i][j];
    }
}

// ---------------- micro-kernel: N-packed f32x2, zero-MOV inner loop ----------------
// acc[i][p] = packed {C[r0+i][c0+2p], C[r0+i][c0+2p+1]}
template<int BM, int BN, int TM, int TN>
__device__ __forceinline__ void mac_block(
    const float (&As2)[16][2 * BM], const float (&Ws)[16][BN],
    int r0, int c0, ull (&acc)[TM][TN / 2])
{
#pragma unroll
    for (int k = 0; k < 16; k++) {
        ull ad[TM];
#pragma unroll
        for (int i = 0; i < TM; i += 2) {
            ulonglong2 t = *(const ulonglong2*)&As2[k][2 * (r0 + i)];
            ad[i] = t.x; ad[i + 1] = t.y;
        }
        ull wv[TN / 2];
#pragma unroll
        for (int p = 0; p < TN / 2; p += 2) {
            ulonglong2 w = *(const ulonglong2*)&Ws[k][c0 + 2 * p];
            wv[p] = w.x; wv[p + 1] = w.y;
        }
#pragma unroll
        for (int i = 0; i < TM; i++)
#pragma unroll
            for (int p = 0; p < TN / 2; p++)
                ffma2(acc[i][p], ad[i], wv[p]);
    }
}

// ---------------- K-staged double-buffered mainloop ----------------
template<int NT, int BM, int BN, int TM, int TN>
__device__ __forceinline__ void gemm_mainloop(
    const float* __restrict__ A, long lda,
    const float* __restrict__ W, int K,
    const int* __restrict__ gather,
    int m0, int n0, int tid, int r0, int c0,
    float (&As2)[2][16][2 * BM], float (&Ws)[2][16][BN],
    ull (&acc)[TM][TN / 2])
{
    constexpr int NCA = BM * 4 / NT;
    constexpr int NCW = BN * 4 / NT;
    float ar[NCA][4], wr[NCW][4];
    int nkb = (K + 15) / 16;

    load_tile<NT, BM>(A, lda, gather, m0, K, 0, tid, ar);
    load_tile<NT, BN>(W, (long)K, nullptr, n0, K, 0, tid, wr);
    store_a_dup<NT, BM>(As2[0], tid, ar);
    store_w<NT, BN>(Ws[0], tid, wr);
    __syncthreads();

    int buf = 0;
    for (int kb = 0; kb < nkb; kb++) {
        bool hn = (kb + 1 < nkb);
        if (hn) {
            load_tile<NT, BM>(A, lda, gather, m0, K, (kb + 1) * 16, tid, ar);
            load_tile<NT, BN>(W, (long)K, nullptr, n0, K, (kb + 1) * 16, tid, wr);
        }
        mac_block<BM, BN, TM, TN>(As2[buf], Ws[buf], r0, c0, acc);
        if (hn) {
            store_a_dup<NT, BM>(As2[buf ^ 1], tid, ar);
            store_w<NT, BN>(Ws[buf ^ 1], tid, wr);
        }
        __syncthreads();
        buf ^= 1;
    }
}

// ---------------- generic GEMM kernel: up to 3 balanced jobs via blockIdx.z ----------------
template<int NT, int BM, int BN, int TM, int TN>
__global__ void __launch_bounds__(NT)
gemm3_kernel(GemmJob j0, GemmJob j1, GemmJob j2)
{
    GemmJob j = (blockIdx.z == 0) ? j0 : ((blockIdx.z == 1) ? j1 : j2);
    if (!j.valid) return;

    __shared__ float As2[2][16][2 * BM];
    __shared__ float Ws[2][16][BN];

    constexpr int CT = BN / TN;
    int tid = threadIdx.x;
    int m0 = blockIdx.y * BM;
    int n0 = blockIdx.x * BN;
    int ty = tid / CT, tx = tid % CT;
    int r0 = ty * TM, c0 = tx * TN;

    ull acc[TM][TN / 2] = {};
    gemm_mainloop<NT, BM, BN, TM, TN>(j.A, j.lda, j.W, j.K, j.gather,
                                      m0, n0, tid, r0, c0, As2, Ws, acc);

#pragma unroll
    for (int i = 0; i < TM; i++) {
        int m = m0 + r0 + i;
        float o[TN];
#pragma unroll
        for (int p = 0; p < TN / 2; p++)
            unpk(acc[i][p], o[2 * p], o[2 * p + 1]);
#pragma unroll
        for (int q = 0; q < TN; q++) {
            float v = o[q];
            int n = n0 + c0 + q;
            if (j.bias)   v += __ldg(&j.bias[n]);
            if (j.addmat) v += __ldg(&j.addmat[(long)m * j.ldadd + n]);
            if (j.act)    v = tanhf(v);
            o[q] = v;
        }
#pragma unroll
        for (int q = 0; q < TN; q += 4)
            *(float4*)&j.C[(long)m * j.ldc + n0 + c0 + q] = *(const float4*)&o[q];
    }
}

// ---------------- logits + argmax (R2-proven, one block per batch row) ----------------
__global__ void __launch_bounds__(256)
logits_kernel(const float* __restrict__ d1, const float* __restrict__ fcW,
              const float* __restrict__ fcb, float* __restrict__ out,
              int step, int* __restrict__ tok)
{
    __shared__ float hs[Hc];
    __shared__ float vals[Vc];
    int b = blockIdx.x, tid = threadIdx.x;

    *(float4*)&hs[tid * 4] = *(const float4*)&d1[(size_t)b * Hc + tid * 4];
    __syncthreads();

    int warp = tid >> 5, lane = tid & 31;
#pragma unroll
    for (int j = 0; j < 8; j++) {
        int v = warp * 8 + j;
        const float4* wp = (const float4*)&fcW[(size_t)v * Hc];
        float s = 0.0f;
#pragma unroll
        for (int i = 0; i < 8; i++) {
            float4 w4 = __ldg(&wp[lane + i * 32]);
            float4 h4 = *(const float4*)&hs[(lane + i * 32) * 4];
            s += w4.x * h4.x + w4.y * h4.y + w4.z * h4.z + w4.w * h4.w;
        }
#pragma unroll
        for (int o = 16; o; o >>= 1) s += __shfl_xor_sync(0xffffffffu, s, o);
        if (lane == 0) {
            s += fcb[v];
            vals[v] = s;
            out[((size_t)b * Vc + (size_t)v) * ML + (size_t)step] = s;
        }
    }
    __syncthreads();
    if (tid == 0) {
        float best = vals[0]; int bi = 0;
#pragma unroll
        for (int i = 1; i < Vc; i++)
            if (vals[i] > best) { best = vals[i]; bi = i; }   // first-max = jnp.argmax
        tok[b] = bi;
    }
}

__global__ void init_kernel(float* __restrict__ z, int* __restrict__ tok)
{
    int i = blockIdx.x * blockDim.x + threadIdx.x;
    if (i < Bc * Hc) z[i] = 0.0f;
    if (i < Bc) tok[i] = 0;
}

__global__ void copy_hidden_kernel(const float* __restrict__ d0,
                                   const float* __restrict__ d1,
                                   float* __restrict__ o)
{
    int i = blockIdx.x * blockDim.x + threadIdx.x;
    if (i < Bc * Hc) {
        o[i] = d0[i];
        o[Bc * Hc + i] = d1[i];
    }
}

// ---------------- host ----------------
extern "C" void kernel_launch(void* const* d_in, const int* in_sizes, int n_in,
                              void* d_out, int out_size)
{
    (void)in_sizes; (void)n_in; (void)out_size;
    const float* x     = (const float*)d_in[0];
    const float* emb   = (const float*)d_in[1];
    const float* eWih0 = (const float*)d_in[2];
    const float* eWhh0 = (const float*)d_in[3];
    const float* eb0   = (const float*)d_in[4];
    const float* eWih1 = (const float*)d_in[5];
    const float* eWhh1 = (const float*)d_in[6];
    const float* eb1   = (const float*)d_in[7];
    const float* dWih0 = (const float*)d_in[8];
    const float* dWhh0 = (const float*)d_in[9];
    const float* db0   = (const float*)d_in[10];
    const float* dWih1 = (const float*)d_in[11];
    const float* dWhh1 = (const float*)d_in[12];
    const float* db1   = (const float*)d_in[13];
    const float* fcW   = (const float*)d_in[14];
    const float* fcb   = (const float*)d_in[15];
    float* out = (float*)d_out;

    float *U0, *h0base, *h1base, *Vbase, *d0base, *d1base, *P0, *P1, *zero;
    int* tok;
    cudaGetSymbolAddress((void**)&U0, g_U0);
    cudaGetSymbolAddress((void**)&h0base, g_h0);
    cudaGetSymbolAddress((void**)&h1base, g_h1);
    cudaGetSymbolAddress((void**)&Vbase, g_V);
    cudaGetSymbolAddress((void**)&d0base, g_d0);
    cudaGetSymbolAddress((void**)&d1base, g_d1);
    cudaGetSymbolAddress((void**)&P0, g_P0);
    cudaGetSymbolAddress((void**)&P1, g_P1);
    cudaGetSymbolAddress((void**)&zero, g_zero);
    cudaGetSymbolAddress((void**)&tok, g_tok);

    float* h0b[2] = { h0base, h0base + (size_t)Bc * Hc };
    float* h1b[2] = { h1base, h1base + (size_t)Bc * Hc };
    float* Vb[2]  = { Vbase,  Vbase  + (size_t)Bc * Hc };
    float* d0b[2] = { d0base, d0base + (size_t)Bc * Hc };
    float* d1b[2] = { d1base, d1base + (size_t)Bc * Hc };

    init_kernel<<<(Bc * Hc + 255) / 256, 256>>>(zero, tok);

    GemmJob inv = {}; inv.valid = 0;

    // ---- precompute U0 = x_flat @ eWih0^T + b0 (high-intensity TM=8 config) ----
    {
        GemmJob j = {};
        j.A = x; j.lda = Lc; j.W = eWih0; j.K = Lc;
        j.bias = eb0;
        j.C = U0; j.ldc = Hc; j.act = 0; j.valid = 1;
        gemm3_kernel<256, 128, 64, 8, 4>
            <<<dim3(Hc / 64, (Bc * Tc) / 128, 1), 256>>>(j, inv, inv);
    }

    // ---- encoder: 3 balanced K=1024 units per launch (skewed chain) ----
    // launch t: A) h0_t = tanh(h0_{t-1}@Whh0 + U0[:,t])
    //           B) V_{t-1} = h0_{t-1}@Wih1 + b1
    //           C) h1_{t-2} = tanh(h1_{t-3}@Whh1 + V_{t-2})
    // t == Tc: slot A computes decoder bootstrap P0 = h0_final @ dWhh0
    for (int t = 0; t <= Tc + 1; t++) {
        GemmJob jA = inv, jB = inv, jC = inv;
        if (t < Tc) {
            jA.A = (t == 0) ? zero : h0b[(t - 1) & 1];
            jA.lda = Hc; jA.W = eWhh0; jA.K = Hc;
            jA.addmat = U0 + (size_t)t * Hc; jA.ldadd = (long)Tc * Hc;
            jA.C = h0b[t & 1]; jA.ldc = Hc; jA.act = 1; jA.valid = 1;
        } else if (t == Tc) {
            jA.A = h0b[(Tc - 1) & 1]; jA.lda = Hc; jA.W = dWhh0; jA.K = Hc;
            jA.C = P0; jA.ldc = Hc; jA.act = 0; jA.valid = 1;
        }
        if (t >= 1 && t <= Tc) {
            int s = t - 1;
            jB.A = h0b[s & 1]; jB.lda = Hc; jB.W = eWih1; jB.K = Hc;
            jB.bias = eb1;
            jB.C = Vb[s & 1]; jB.ldc = Hc; jB.act = 0; jB.valid = 1;
        }
        if (t >= 2) {
            int s = t - 2;
            jC.A = (s == 0) ? zero : h1b[(s - 1) & 1];
            jC.lda = Hc; jC.W = eWhh1; jC.K = Hc;
            jC.addmat = Vb[s & 1]; jC.ldadd = Hc;
            jC.C = h1b[s & 1]; jC.ldc = Hc; jC.act = 1; jC.valid = 1;
        }
        gemm3_kernel<256, 64, 64, 4, 4>
            <<<dim3(Hc / 64, Bc / 64, 3), 256>>>(jA, jB, jC);
    }

    // ---- decoder: 2 balanced K=1024 units per GEMM launch (P0/P1 pre-rotation) ----
    const float* d1prev = h1b[(Tc - 1) & 1];
    for (int s = 0; s < ML; s++) {
        float* d0cur = d0b[s & 1];
        float* d1cur = d1b[s & 1];
        {   // L1: d0_s = tanh(emb[tok]@Wih0 + P0 + b0);  P1 = d1_{s-1}@Whh1
            GemmJob jA = inv, jB = inv;
            jA.A = emb; jA.lda = Hc; jA.W = dWih0; jA.K = Hc;
            jA.gather = tok;
            jA.bias = db0; jA.addmat = P0; jA.ldadd = Hc;
            jA.C = d0cur; jA.ldc = Hc; jA.act = 1; jA.valid = 1;
            jB.A = d1prev; jB.lda = Hc; jB.W = dWhh1; jB.K = Hc;
            jB.C = P1; jB.ldc = Hc; jB.act = 0; jB.valid = 1;
            gemm3_kernel<256, 64, 64, 4, 4>
                <<<dim3(Hc / 64, Bc / 64, 2), 256>>>(jA, jB, inv);
        }
        {   // L2: d1_s = tanh(d0_s@Wih1 + P1 + b1);  P0 = d0_s@Whh0 (for s+1)
            GemmJob jA = inv, jB = inv;
            jA.A = d0cur; jA.lda = Hc; jA.W = dWih1; jA.K = Hc;
            jA.bias = db1; jA.addmat = P1; jA.ldadd = Hc;
            jA.C = d1cur; jA.ldc = Hc; jA.act = 1; jA.valid = 1;
            jB.A = d0cur; jB.lda = Hc; jB.W = dWhh0; jB.K = Hc;
            jB.C = P0; jB.ldc = Hc; jB.act = 0; jB.valid = 1;
            gemm3_kernel<256, 64, 64, 4, 4>
                <<<dim3(Hc / 64, Bc / 64, 2), 256>>>(jA, jB, inv);
        }
        logits_kernel<<<Bc, 256>>>(d1cur, fcW, fcb, out, s, tok);
        d1prev = d1cur;
    }

    copy_hidden_kernel<<<(Bc * Hc + 255) / 256, 256>>>(
        d0b[(ML - 1) & 1], d1b[(ML - 1) & 1], out + (size_t)Bc * Vc * ML);
}

// round 9
// speedup vs baseline: 1.0706x; 1.0706x over previous
#include <cuda_runtime.h>
#include <cstdint>
#include <cstddef>

// Problem dims
#define Bc 256
#define Tc 128
#define Hc 1024
#define Vc 64
#define Lc 457
#define ML 64

typedef unsigned long long ull;

// ---------------- device scratch (no allocs allowed) ----------------
__device__ float g_U0[(size_t)Bc * Tc * Hc];   // x @ enc_Wih0^T + b0
__device__ float g_h0[2][Bc * Hc];
__device__ float g_h1[2][Bc * Hc];
__device__ float g_V [2][Bc * Hc];             // h0_t @ eWih1^T + b1
__device__ float g_d0[2][Bc * Hc];
__device__ float g_d1[2][Bc * Hc];
__device__ float g_P0[Bc * Hc];                // d0_{s-1} @ dWhh0^T (pre-rotated)
__device__ float g_P1[Bc * Hc];                // d1_{s-1} @ dWhh1^T
__device__ float g_zero[Bc * Hc];
__device__ int   g_tok[Bc];

// ---------------- packed fp32 helpers (sm_103a f32x2) ----------------
__device__ __forceinline__ ull dup2(float a) {
    ull r;
    asm("mov.b64 %0, {%1, %1};" : "=l"(r) : "r"(__float_as_uint(a)));
    return r;
}
__device__ __forceinline__ void ffma2(ull& d, ull a, ull b) {
    asm("fma.rn.f32x2 %0, %1, %2, %0;" : "+l"(d) : "l"(a), "l"(b));
}
__device__ __forceinline__ void unpk(ull v, float& lo, float& hi) {
    unsigned int a, b;
    asm("mov.b64 {%0, %1}, %2;" : "=r"(a), "=r"(b) : "l"(v));
    lo = __uint_as_float(a);
    hi = __uint_as_float(b);
}

// ---------------- GEMM job descriptor (single source) ----------------
struct GemmJob {
    const float* A; long lda; const float* W;  // C = act(A @ W^T + bias + addmat)
    int K;
    const int* gather;                          // optional row gather on A
    const float* bias; const float* addmat; long ldadd;
    float* C; long ldc; int act; int valid;
};

// ---------------- tile loaders (BR rows x 16 k-cols) ----------------
template<int NT, int BR>
__device__ __forceinline__ void load_tile(
    const float* __restrict__ A, long lda, const int* __restrict__ gather,
    int r_base, int K, int k0, int tid, float (&r)[BR * 4 / NT][4])
{
    constexpr int NC = BR * 4 / NT;
#pragma unroll
    for (int i = 0; i < NC; i++) {
        int cid = tid + i * NT;
        int row = cid >> 2, kq = cid & 3;
        int kk = k0 + kq * 4;
        long arow = gather ? (long)__ldg(&gather[r_base + row]) : (long)(r_base + row);
        const float* p = A + arow * lda + kk;
        if (kk + 3 < K && ((((uintptr_t)p) & 15u) == 0)) {
            float4 v = *(const float4*)p;
            r[i][0] = v.x; r[i][1] = v.y; r[i][2] = v.z; r[i][3] = v.w;
        } else {
#pragma unroll
            for (int j = 0; j < 4; j++)
                r[i][j] = (kk + j < K) ? __ldg(p + j) : 0.0f;
        }
    }
}

template<int NT, int BR>
__device__ __forceinline__ void store_tile(
    float (&S)[16][BR], int tid, const float (&r)[BR * 4 / NT][4])
{
    constexpr int NC = BR * 4 / NT;
#pragma unroll
    for (int i = 0; i < NC; i++) {
        int cid = tid + i * NT;
        int row = cid >> 2, kq = cid & 3;
#pragma unroll
        for (int j = 0; j < 4; j++)
            S[kq * 4 + j][row] = r[i][j];
    }
}

// ---------------- micro-kernel: TM x TN per thread via f32x2 ----------------
// crossbar-optimized at TM=8: 3 LDS.128 per 1024 warp-MACs
template<int BM, int BN, int TM, int TN>
__device__ __forceinline__ void mac_block(
    const float (&As)[16][BM], const float (&Ws)[16][BN],
    int r0, int c0, ull (&acc)[TM][TN / 2])
{
#pragma unroll
    for (int k = 0; k < 16; k++) {
        ull ad[TM];
#pragma unroll
        for (int i = 0; i < TM; i += 4) {
            float4 av = *(const float4*)&As[k][r0 + i];
            ad[i + 0] = dup2(av.x);
            ad[i + 1] = dup2(av.y);
            ad[i + 2] = dup2(av.z);
            ad[i + 3] = dup2(av.w);
        }
        ull wv[TN / 2];
#pragma unroll
        for (int p = 0; p < TN / 2; p += 2) {
            ulonglong2 w2 = *(const ulonglong2*)&Ws[k][c0 + 2 * p];
            wv[p] = w2.x;
            wv[p + 1] = w2.y;
        }
#pragma unroll
        for (int i = 0; i < TM; i++)
#pragma unroll
            for (int p = 0; p < TN / 2; p++)
                ffma2(acc[i][p], ad[i], wv[p]);
    }
}

// ---------------- K-staged double-buffered mainloop ----------------
template<int NT, int BM, int BN, int TM, int TN>
__device__ __forceinline__ void gemm_mainloop(
    const float* __restrict__ A, long lda,
    const float* __restrict__ W, int K,
    const int* __restrict__ gather,
    int m0, int n0, int tid, int r0, int c0,
    float (&As)[2][16][BM], float (&Ws)[2][16][BN],
    ull (&acc)[TM][TN / 2])
{
    constexpr int NCA = BM * 4 / NT;
    constexpr int NCW = BN * 4 / NT;
    float ar[NCA][4], wr[NCW][4];
    int nkb = (K + 15) / 16;

    load_tile<NT, BM>(A, lda, gather, m0, K, 0, tid, ar);
    load_tile<NT, BN>(W, (long)K, nullptr, n0, K, 0, tid, wr);
    store_tile<NT, BM>(As[0], tid, ar);
    store_tile<NT, BN>(Ws[0], tid, wr);
    __syncthreads();

    int buf = 0;
    for (int kb = 0; kb < nkb; kb++) {
        bool hn = (kb + 1 < nkb);
        if (hn) {
            load_tile<NT, BM>(A, lda, gather, m0, K, (kb + 1) * 16, tid, ar);
            load_tile<NT, BN>(W, (long)K, nullptr, n0, K, (kb + 1) * 16, tid, wr);
        }
        mac_block<BM, BN, TM, TN>(As[buf], Ws[buf], r0, c0, acc);
        if (hn) {
            store_tile<NT, BM>(As[buf ^ 1], tid, ar);
            store_tile<NT, BN>(Ws[buf ^ 1], tid, wr);
        }
        __syncthreads();
        buf ^= 1;
    }
}

// ---------------- generic GEMM kernel: up to 3 balanced jobs via blockIdx.z ----------------
template<int NT, int BM, int BN, int TM, int TN>
__global__ void __launch_bounds__(NT)
gemm3_kernel(GemmJob j0, GemmJob j1, GemmJob j2)
{
    GemmJob j = (blockIdx.z == 0) ? j0 : ((blockIdx.z == 1) ? j1 : j2);
    if (!j.valid) return;

    __shared__ float As[2][16][BM];
    __shared__ float Ws[2][16][BN];

    constexpr int CT = BN / TN;
    int tid = threadIdx.x;
    int m0 = blockIdx.y * BM;
    int n0 = blockIdx.x * BN;
    int ty = tid / CT, tx = tid % CT;
    int r0 = ty * TM, c0 = tx * TN;

    ull acc[TM][TN / 2] = {};
    gemm_mainloop<NT, BM, BN, TM, TN>(j.A, j.lda, j.W, j.K, j.gather,
                                      m0, n0, tid, r0, c0, As, Ws, acc);

#pragma unroll
    for (int i = 0; i < TM; i++) {
        int m = m0 + r0 + i;
        float o[TN];
#pragma unroll
        for (int p = 0; p < TN / 2; p++)
            unpk(acc[i][p], o[2 * p], o[2 * p + 1]);
#pragma unroll
        for (int q = 0; q < TN; q++) {
            float v = o[q];
            int n = n0 + c0 + q;
            if (j.bias)   v += __ldg(&j.bias[n]);
            if (j.addmat) v += __ldg(&j.addmat[(long)m * j.ldadd + n]);
            if (j.act)    v = tanhf(v);
            o[q] = v;
        }
#pragma unroll
        for (int q = 0; q < TN; q += 4)
            *(float4*)&j.C[(long)m * j.ldc + n0 + c0 + q] = *(const float4*)&o[q];
    }
}

// ---------------- logits + argmax (proven, one block per batch row) ----------------
__global__ void __launch_bounds__(256)
logits_kernel(const float* __restrict__ d1, const float* __restrict__ fcW,
              const float* __restrict__ fcb, float* __restrict__ out,
              int step, int* __restrict__ tok)
{
    __shared__ float hs[Hc];
    __shared__ float vals[Vc];
    int b = blockIdx.x, tid = threadIdx.x;

    *(float4*)&hs[tid * 4] = *(const float4*)&d1[(size_t)b * Hc + tid * 4];
    __syncthreads();

    int warp = tid >> 5, lane = tid & 31;
#pragma unroll
    for (int j = 0; j < 8; j++) {
        int v = warp * 8 + j;
        const float4* wp = (const float4*)&fcW[(size_t)v * Hc];
        float s = 0.0f;
#pragma unroll
        for (int i = 0; i < 8; i++) {
            float4 w4 = __ldg(&wp[lane + i * 32]);
            float4 h4 = *(const float4*)&hs[(lane + i * 32) * 4];
            s += w4.x * h4.x + w4.y * h4.y + w4.z * h4.z + w4.w * h4.w;
        }
#pragma unroll
        for (int o = 16; o; o >>= 1) s += __shfl_xor_sync(0xffffffffu, s, o);
        if (lane == 0) {
            s += fcb[v];
            vals[v] = s;
            out[((size_t)b * Vc + (size_t)v) * ML + (size_t)step] = s;
        }
    }
    __syncthreads();
    if (tid == 0) {
        float best = vals[0]; int bi = 0;
#pragma unroll
        for (int i = 1; i < Vc; i++)
            if (vals[i] > best) { best = vals[i]; bi = i; }   // first-max = jnp.argmax
        tok[b] = bi;
    }
}

__global__ void init_kernel(float* __restrict__ z, int* __restrict__ tok)
{
    int i = blockIdx.x * blockDim.x + threadIdx.x;
    if (i < Bc * Hc) z[i] = 0.0f;
    if (i < Bc) tok[i] = 0;
}

__global__ void copy_hidden_kernel(const float* __restrict__ d0,
                                   const float* __restrict__ d1,
                                   float* __restrict__ o)
{
    int i = blockIdx.x * blockDim.x + threadIdx.x;
    if (i < Bc * Hc) {
        o[i] = d0[i];
        o[Bc * Hc + i] = d1[i];
    }
}

// ---------------- host ----------------
extern "C" void kernel_launch(void* const* d_in, const int* in_sizes, int n_in,
                              void* d_out, int out_size)
{
    (void)in_sizes; (void)n_in; (void)out_size;
    const float* x     = (const float*)d_in[0];
    const float* emb   = (const float*)d_in[1];
    const float* eWih0 = (const float*)d_in[2];
    const float* eWhh0 = (const float*)d_in[3];
    const float* eb0   = (const float*)d_in[4];
    const float* eWih1 = (const float*)d_in[5];
    const float* eWhh1 = (const float*)d_in[6];
    const float* eb1   = (const float*)d_in[7];
    const float* dWih0 = (const float*)d_in[8];
    const float* dWhh0 = (const float*)d_in[9];
    const float* db0   = (const float*)d_in[10];
    const float* dWih1 = (const float*)d_in[11];
    const float* dWhh1 = (const float*)d_in[12];
    const float* db1   = (const float*)d_in[13];
    const float* fcW   = (const float*)d_in[14];
    const float* fcb   = (const float*)d_in[15];
    float* out = (float*)d_out;

    float *U0, *h0base, *h1base, *Vbase, *d0base, *d1base, *P0, *P1, *zero;
    int* tok;
    cudaGetSymbolAddress((void**)&U0, g_U0);
    cudaGetSymbolAddress((void**)&h0base, g_h0);
    cudaGetSymbolAddress((void**)&h1base, g_h1);
    cudaGetSymbolAddress((void**)&Vbase, g_V);
    cudaGetSymbolAddress((void**)&d0base, g_d0);
    cudaGetSymbolAddress((void**)&d1base, g_d1);
    cudaGetSymbolAddress((void**)&P0, g_P0);
    cudaGetSymbolAddress((void**)&P1, g_P1);
    cudaGetSymbolAddress((void**)&zero, g_zero);
    cudaGetSymbolAddress((void**)&tok, g_tok);

    float* h0b[2] = { h0base, h0base + (size_t)Bc * Hc };
    float* h1b[2] = { h1base, h1base + (size_t)Bc * Hc };
    float* Vb[2]  = { Vbase,  Vbase  + (size_t)Bc * Hc };
    float* d0b[2] = { d0base, d0base + (size_t)Bc * Hc };
    float* d1b[2] = { d1base, d1base + (size_t)Bc * Hc };

    init_kernel<<<(Bc * Hc + 255) / 256, 256>>>(zero, tok);

    GemmJob inv = {}; inv.valid = 0;

    // ---- precompute U0 = x_flat @ eWih0^T + b0 ----
    {
        GemmJob j = {};
        j.A = x; j.lda = Lc; j.W = eWih0; j.K = Lc;
        j.bias = eb0;
        j.C = U0; j.ldc = Hc; j.act = 0; j.valid = 1;
        gemm3_kernel<256, 128, 64, 8, 4>
            <<<dim3(Hc / 64, (Bc * Tc) / 128, 1), 256>>>(j, inv, inv);
    }

    // ---- encoder: 3 balanced K=1024 units per launch (skewed chain) ----
    // TM=8 / 64x128 tiles: 96 blocks, single wave, 3 LDS.128 per 1024 warp-MACs
    // launch t: A) h0_t = tanh(h0_{t-1}@Whh0 + U0[:,t])
    //           B) V_{t-1} = h0_{t-1}@Wih1 + b1
    //           C) h1_{t-2} = tanh(h1_{t-3}@Whh1 + V_{t-2})
    // t == Tc: slot A computes decoder bootstrap P0 = h0_final @ dWhh0
    for (int t = 0; t <= Tc + 1; t++) {
        GemmJob jA = inv, jB = inv, jC = inv;
        if (t < Tc) {
            jA.A = (t == 0) ? zero : h0b[(t - 1) & 1];
            jA.lda = Hc; jA.W = eWhh0; jA.K = Hc;
            jA.addmat = U0 + (size_t)t * Hc; jA.ldadd = (long)Tc * Hc;
            jA.C = h0b[t & 1]; jA.ldc = Hc; jA.act = 1; jA.valid = 1;
        } else if (t == Tc) {
            jA.A = h0b[(Tc - 1) & 1]; jA.lda = Hc; jA.W = dWhh0; jA.K = Hc;
            jA.C = P0; jA.ldc = Hc; jA.act = 0; jA.valid = 1;
        }
        if (t >= 1 && t <= Tc) {
            int s = t - 1;
            jB.A = h0b[s & 1]; jB.lda = Hc; jB.W = eWih1; jB.K = Hc;
            jB.bias = eb1;
            jB.C = Vb[s & 1]; jB.ldc = Hc; jB.act = 0; jB.valid = 1;
        }
        if (t >= 2) {
            int s = t - 2;
            jC.A = (s == 0) ? zero : h1b[(s - 1) & 1];
            jC.lda = Hc; jC.W = eWhh1; jC.K = Hc;
            jC.addmat = Vb[s & 1]; jC.ldadd = Hc;
            jC.C = h1b[s & 1]; jC.ldc = Hc; jC.act = 1; jC.valid = 1;
        }
        gemm3_kernel<256, 64, 128, 8, 4>
            <<<dim3(Hc / 128, Bc / 64, 3), 256>>>(jA, jB, jC);
    }

    // ---- decoder: 2 balanced K=1024 units per GEMM launch (P0/P1 pre-rotation) ----
    const float* d1prev = h1b[(Tc - 1) & 1];
    for (int s = 0; s < ML; s++) {
        float* d0cur = d0b[s & 1];
        float* d1cur = d1b[s & 1];
        {   // L1: d0_s = tanh(emb[tok]@Wih0 + P0 + b0);  P1 = d1_{s-1}@Whh1
            GemmJob jA = inv, jB = inv;
            jA.A = emb; jA.lda = Hc; jA.W = dWih0; jA.K = Hc;
            jA.gather = tok;
            jA.bias = db0; jA.addmat = P0; jA.ldadd = Hc;
            jA.C = d0cur; jA.ldc = Hc; jA.act = 1; jA.valid = 1;
            jB.A = d1prev; jB.lda = Hc; jB.W = dWhh1; jB.K = Hc;
            jB.C = P1; jB.ldc = Hc; jB.act = 0; jB.valid = 1;
            gemm3_kernel<256, 64, 128, 8, 4>
                <<<dim3(Hc / 128, Bc / 64, 2), 256>>>(jA, jB, inv);
        }
        {   // L2: d1_s = tanh(d0_s@Wih1 + P1 + b1);  P0 = d0_s@Whh0 (for s+1)
            GemmJob jA = inv, jB = inv;
            jA.A = d0cur; jA.lda = Hc; jA.W = dWih1; jA.K = Hc;
            jA.bias = db1; jA.addmat = P1; jA.ldadd = Hc;
            jA.C = d1cur; jA.ldc = Hc; jA.act = 1; jA.valid = 1;
            jB.A = d0cur; jB.lda = Hc; jB.W = dWhh0; jB.K = Hc;
            jB.C = P0; jB.ldc = Hc; jB.act = 0; jB.valid = 1;
            gemm3_kernel<256, 64, 128, 8, 4>
                <<<dim3(Hc / 128, Bc / 64, 2), 256>>>(jA, jB, inv);
        }
        logits_kernel<<<Bc, 256>>>(d1cur, fcW, fcb, out, s, tok);
        d1prev = d1cur;
    }

    copy_hidden_kernel<<<(Bc * Hc + 255) / 256, 256>>>(
        d0b[(ML - 1) & 1], d1b[(ML - 1) & 1], out + (size_t)Bc * Vc * ML);
}

// round 10
// speedup vs baseline: 1.3430x; 1.2545x over previous
#include <cuda_runtime.h>
#include <cstdint>
#include <cstddef>

// Problem dims
#define Bc 256
#define Tc 128
#define Hc 1024
#define Vc 64
#define Lc 457
#define ML 64

typedef unsigned long long ull;

// ---------------- device scratch (no allocs allowed) ----------------
__device__ float g_U0[(size_t)Bc * Tc * Hc];   // x @ enc_Wih0^T + b0
__device__ float g_h0[2][Bc * Hc];
__device__ float g_h1[2][Bc * Hc];
__device__ float g_V [2][Bc * Hc];             // h0_t @ eWih1^T + b1
__device__ float g_d0[2][Bc * Hc];
__device__ float g_d1[2][Bc * Hc];
__device__ float g_P0[Bc * Hc];                // d0_{s-1} @ dWhh0^T (pre-rotated)
__device__ float g_P1[Bc * Hc];                // d1_{s-1} @ dWhh1^T
__device__ float g_zero[Bc * Hc];
__device__ int   g_tok[Bc];

// ---------------- packed fp32 helpers (sm_103a f32x2) ----------------
__device__ __forceinline__ ull dup2(float a) {
    ull r;
    asm("mov.b64 %0, {%1, %1};" : "=l"(r) : "r"(__float_as_uint(a)));
    return r;
}
__device__ __forceinline__ void ffma2(ull& d, ull a, ull b) {
    asm("fma.rn.f32x2 %0, %1, %2, %0;" : "+l"(d) : "l"(a), "l"(b));
}
__device__ __forceinline__ void unpk(ull v, float& lo, float& hi) {
    unsigned int a, b;
    asm("mov.b64 {%0, %1}, %2;" : "=r"(a), "=r"(b) : "l"(v));
    lo = __uint_as_float(a);
    hi = __uint_as_float(b);
}

// ---------------- GEMM job descriptor (single source) ----------------
struct GemmJob {
    const float* A; long lda; const float* W;  // C = act(A @ W^T + bias + addmat)
    int K;
    const int* gather;                          // optional row gather on A
    const float* bias; const float* addmat; long ldadd;
    float* C; long ldc; int act; int valid;
};

// ---------------- tile loaders (BR rows x 16 k-cols) ----------------
template<int NT, int BR>
__device__ __forceinline__ void load_tile(
    const float* __restrict__ A, long lda, const int* __restrict__ gather,
    int r_base, int K, int k0, int tid, float (&r)[BR * 4 / NT][4])
{
    constexpr int NC = BR * 4 / NT;
#pragma unroll
    for (int i = 0; i < NC; i++) {
        int cid = tid + i * NT;
        int row = cid >> 2, kq = cid & 3;
        int kk = k0 + kq * 4;
        long arow = gather ? (long)__ldg(&gather[r_base + row]) : (long)(r_base + row);
        const float* p = A + arow * lda + kk;
        if (kk + 3 < K && ((((uintptr_t)p) & 15u) == 0)) {
            float4 v = *(const float4*)p;
            r[i][0] = v.x; r[i][1] = v.y; r[i][2] = v.z; r[i][3] = v.w;
        } else {
#pragma unroll
            for (int j = 0; j < 4; j++)
                r[i][j] = (kk + j < K) ? __ldg(p + j) : 0.0f;
        }
    }
}

template<int NT, int BR>
__device__ __forceinline__ void store_tile(
    float (&S)[16][BR], int tid, const float (&r)[BR * 4 / NT][4])
{
    constexpr int NC = BR * 4 / NT;
#pragma unroll
    for (int i = 0; i < NC; i++) {
        int cid = tid + i * NT;
        int row = cid >> 2, kq = cid & 3;
#pragma unroll
        for (int j = 0; j < 4; j++)
            S[kq * 4 + j][row] = r[i][j];
    }
}

// ---------------- micro-kernel: SOFTWARE-PIPELINED over k ----------------
// k+1's smem loads issue BEFORE k's MOV/FFMA2 pack -> LDS latency hidden
// by compute issue instead of exposed every k-step.
// Requires TM % 4 == 0, TN == 4.
template<int BM, int BN, int TM, int TN>
__device__ __forceinline__ void mac_block(
    const float (&As)[16][BM], const float (&Ws)[16][BN],
    int r0, int c0, ull (&acc)[TM][TN / 2])
{
    static_assert(TN == 4, "TN must be 4");
    float4 a_cur[TM / 4];
    ulonglong2 w_cur;
#pragma unroll
    for (int i = 0; i < TM / 4; i++)
        a_cur[i] = *(const float4*)&As[0][r0 + 4 * i];
    w_cur = *(const ulonglong2*)&Ws[0][c0];

#pragma unroll
    for (int k = 0; k < 16; k++) {
        float4 a_nxt[TM / 4];
        ulonglong2 w_nxt;
        if (k < 15) {
            // prefetch k+1 FIRST so these LDS issue ahead of the compute pack
#pragma unroll
            for (int i = 0; i < TM / 4; i++)
                a_nxt[i] = *(const float4*)&As[k + 1][r0 + 4 * i];
            w_nxt = *(const ulonglong2*)&Ws[k + 1][c0];
        }

        ull ad[TM];
#pragma unroll
        for (int i = 0; i < TM / 4; i++) {
            ad[4 * i + 0] = dup2(a_cur[i].x);
            ad[4 * i + 1] = dup2(a_cur[i].y);
            ad[4 * i + 2] = dup2(a_cur[i].z);
            ad[4 * i + 3] = dup2(a_cur[i].w);
        }
        ull wv[2];
        wv[0] = w_cur.x;
        wv[1] = w_cur.y;
#pragma unroll
        for (int i = 0; i < TM; i++)
#pragma unroll
            for (int p = 0; p < 2; p++)
                ffma2(acc[i][p], ad[i], wv[p]);

        if (k < 15) {
#pragma unroll
            for (int i = 0; i < TM / 4; i++) a_cur[i] = a_nxt[i];
            w_cur = w_nxt;
        }
    }
}

// ---------------- K-staged double-buffered mainloop ----------------
template<int NT, int BM, int BN, int TM, int TN>
__device__ __forceinline__ void gemm_mainloop(
    const float* __restrict__ A, long lda,
    const float* __restrict__ W, int K,
    const int* __restrict__ gather,
    int m0, int n0, int tid, int r0, int c0,
    float (&As)[2][16][BM], float (&Ws)[2][16][BN],
    ull (&acc)[TM][TN / 2])
{
    constexpr int NCA = BM * 4 / NT;
    constexpr int NCW = BN * 4 / NT;
    float ar[NCA][4], wr[NCW][4];
    int nkb = (K + 15) / 16;

    load_tile<NT, BM>(A, lda, gather, m0, K, 0, tid, ar);
    load_tile<NT, BN>(W, (long)K, nullptr, n0, K, 0, tid, wr);
    store_tile<NT, BM>(As[0], tid, ar);
    store_tile<NT, BN>(Ws[0], tid, wr);
    __syncthreads();

    int buf = 0;
    for (int kb = 0; kb < nkb; kb++) {
        bool hn = (kb + 1 < nkb);
        if (hn) {
            load_tile<NT, BM>(A, lda, gather, m0, K, (kb + 1) * 16, tid, ar);
            load_tile<NT, BN>(W, (long)K, nullptr, n0, K, (kb + 1) * 16, tid, wr);
        }
        mac_block<BM, BN, TM, TN>(As[buf], Ws[buf], r0, c0, acc);
        if (hn) {
            store_tile<NT, BM>(As[buf ^ 1], tid, ar);
            store_tile<NT, BN>(Ws[buf ^ 1], tid, wr);
        }
        __syncthreads();
        buf ^= 1;
    }
}

// ---------------- generic GEMM kernel: up to 3 balanced jobs via blockIdx.z ----------------
template<int NT, int BM, int BN, int TM, int TN>
__global__ void __launch_bounds__(NT)
gemm3_kernel(GemmJob j0, GemmJob j1, GemmJob j2)
{
    GemmJob j = (blockIdx.z == 0) ? j0 : ((blockIdx.z == 1) ? j1 : j2);
    if (!j.valid) return;

    __shared__ float As[2][16][BM];
    __shared__ float Ws[2][16][BN];

    constexpr int CT = BN / TN;
    int tid = threadIdx.x;
    int m0 = blockIdx.y * BM;
    int n0 = blockIdx.x * BN;
    int ty = tid / CT, tx = tid % CT;
    int r0 = ty * TM, c0 = tx * TN;

    ull acc[TM][TN / 2] = {};
    gemm_mainloop<NT, BM, BN, TM, TN>(j.A, j.lda, j.W, j.K, j.gather,
                                      m0, n0, tid, r0, c0, As, Ws, acc);

#pragma unroll
    for (int i = 0; i < TM; i++) {
        int m = m0 + r0 + i;
        float o[TN];
#pragma unroll
        for (int p = 0; p < TN / 2; p++)
            unpk(acc[i][p], o[2 * p], o[2 * p + 1]);
#pragma unroll
        for (int q = 0; q < TN; q++) {
            float v = o[q];
            int n = n0 + c0 + q;
            if (j.bias)   v += __ldg(&j.bias[n]);
            if (j.addmat) v += __ldg(&j.addmat[(long)m * j.ldadd + n]);
            if (j.act)    v = tanhf(v);
            o[q] = v;
        }
#pragma unroll
        for (int q = 0; q < TN; q += 4)
            *(float4*)&j.C[(long)m * j.ldc + n0 + c0 + q] = *(const float4*)&o[q];
    }
}

// ---------------- logits + argmax (proven, one block per batch row) ----------------
__global__ void __launch_bounds__(256)
logits_kernel(const float* __restrict__ d1, const float* __restrict__ fcW,
              const float* __restrict__ fcb, float* __restrict__ out,
              int step, int* __restrict__ tok)
{
    __shared__ float hs[Hc];
    __shared__ float vals[Vc];
    int b = blockIdx.x, tid = threadIdx.x;

    *(float4*)&hs[tid * 4] = *(const float4*)&d1[(size_t)b * Hc + tid * 4];
    __syncthreads();

    int warp = tid >> 5, lane = tid & 31;
#pragma unroll
    for (int j = 0; j < 8; j++) {
        int v = warp * 8 + j;
        const float4* wp = (const float4*)&fcW[(size_t)v * Hc];
        float s = 0.0f;
#pragma unroll
        for (int i = 0; i < 8; i++) {
            float4 w4 = __ldg(&wp[lane + i * 32]);
            float4 h4 = *(const float4*)&hs[(lane + i * 32) * 4];
            s += w4.x * h4.x + w4.y * h4.y + w4.z * h4.z + w4.w * h4.w;
        }
#pragma unroll
        for (int o = 16; o; o >>= 1) s += __shfl_xor_sync(0xffffffffu, s, o);
        if (lane == 0) {
            s += fcb[v];
            vals[v] = s;
            out[((size_t)b * Vc + (size_t)v) * ML + (size_t)step] = s;
        }
    }
    __syncthreads();
    if (tid == 0) {
        float best = vals[0]; int bi = 0;
#pragma unroll
        for (int i = 1; i < Vc; i++)
            if (vals[i] > best) { best = vals[i]; bi = i; }   // first-max = jnp.argmax
        tok[b] = bi;
    }
}

__global__ void init_kernel(float* __restrict__ z, int* __restrict__ tok)
{
    int i = blockIdx.x * blockDim.x + threadIdx.x;
    if (i < Bc * Hc) z[i] = 0.0f;
    if (i < Bc) tok[i] = 0;
}

__global__ void copy_hidden_kernel(const float* __restrict__ d0,
                                   const float* __restrict__ d1,
                                   float* __restrict__ o)
{
    int i = blockIdx.x * blockDim.x + threadIdx.x;
    if (i < Bc * Hc) {
        o[i] = d0[i];
        o[Bc * Hc + i] = d1[i];
    }
}

// ---------------- host ----------------
extern "C" void kernel_launch(void* const* d_in, const int* in_sizes, int n_in,
                              void* d_out, int out_size)
{
    (void)in_sizes; (void)n_in; (void)out_size;
    const float* x     = (const float*)d_in[0];
    const float* emb   = (const float*)d_in[1];
    const float* eWih0 = (const float*)d_in[2];
    const float* eWhh0 = (const float*)d_in[3];
    const float* eb0   = (const float*)d_in[4];
    const float* eWih1 = (const float*)d_in[5];
    const float* eWhh1 = (const float*)d_in[6];
    const float* eb1   = (const float*)d_in[7];
    const float* dWih0 = (const float*)d_in[8];
    const float* dWhh0 = (const float*)d_in[9];
    const float* db0   = (const float*)d_in[10];
    const float* dWih1 = (const float*)d_in[11];
    const float* dWhh1 = (const float*)d_in[12];
    const float* db1   = (const float*)d_in[13];
    const float* fcW   = (const float*)d_in[14];
    const float* fcb   = (const float*)d_in[15];
    float* out = (float*)d_out;

    float *U0, *h0base, *h1base, *Vbase, *d0base, *d1base, *P0, *P1, *zero;
    int* tok;
    cudaGetSymbolAddress((void**)&U0, g_U0);
    cudaGetSymbolAddress((void**)&h0base, g_h0);
    cudaGetSymbolAddress((void**)&h1base, g_h1);
    cudaGetSymbolAddress((void**)&Vbase, g_V);
    cudaGetSymbolAddress((void**)&d0base, g_d0);
    cudaGetSymbolAddress((void**)&d1base, g_d1);
    cudaGetSymbolAddress((void**)&P0, g_P0);
    cudaGetSymbolAddress((void**)&P1, g_P1);
    cudaGetSymbolAddress((void**)&zero, g_zero);
    cudaGetSymbolAddress((void**)&tok, g_tok);

    float* h0b[2] = { h0base, h0base + (size_t)Bc * Hc };
    float* h1b[2] = { h1base, h1base + (size_t)Bc * Hc };
    float* Vb[2]  = { Vbase,  Vbase  + (size_t)Bc * Hc };
    float* d0b[2] = { d0base, d0base + (size_t)Bc * Hc };
    float* d1b[2] = { d1base, d1base + (size_t)Bc * Hc };

    init_kernel<<<(Bc * Hc + 255) / 256, 256>>>(zero, tok);

    GemmJob inv = {}; inv.valid = 0;

    // ---- precompute U0 = x_flat @ eWih0^T + b0 ----
    {
        GemmJob j = {};
        j.A = x; j.lda = Lc; j.W = eWih0; j.K = Lc;
        j.bias = eb0;
        j.C = U0; j.ldc = Hc; j.act = 0; j.valid = 1;
        gemm3_kernel<256, 128, 64, 8, 4>
            <<<dim3(Hc / 64, (Bc * Tc) / 128, 1), 256>>>(j, inv, inv);
    }

    // ---- encoder: 3 balanced K=1024 units per launch (skewed chain) ----
    // launch t: A) h0_t = tanh(h0_{t-1}@Whh0 + U0[:,t])
    //           B) V_{t-1} = h0_{t-1}@Wih1 + b1
    //           C) h1_{t-2} = tanh(h1_{t-3}@Whh1 + V_{t-2})
    // t == Tc: slot A computes decoder bootstrap P0 = h0_final @ dWhh0
    for (int t = 0; t <= Tc + 1; t++) {
        GemmJob jA = inv, jB = inv, jC = inv;
        if (t < Tc) {
            jA.A = (t == 0) ? zero : h0b[(t - 1) & 1];
            jA.lda = Hc; jA.W = eWhh0; jA.K = Hc;
            jA.addmat = U0 + (size_t)t * Hc; jA.ldadd = (long)Tc * Hc;
            jA.C = h0b[t & 1]; jA.ldc = Hc; jA.act = 1; jA.valid = 1;
        } else if (t == Tc) {
            jA.A = h0b[(Tc - 1) & 1]; jA.lda = Hc; jA.W = dWhh0; jA.K = Hc;
            jA.C = P0; jA.ldc = Hc; jA.act = 0; jA.valid = 1;
        }
        if (t >= 1 && t <= Tc) {
            int s = t - 1;
            jB.A = h0b[s & 1]; jB.lda = Hc; jB.W = eWih1; jB.K = Hc;
            jB.bias = eb1;
            jB.C = Vb[s & 1]; jB.ldc = Hc; jB.act = 0; jB.valid = 1;
        }
        if (t >= 2) {
            int s = t - 2;
            jC.A = (s == 0) ? zero : h1b[(s - 1) & 1];
            jC.lda = Hc; jC.W = eWhh1; jC.K = Hc;
            jC.addmat = Vb[s & 1]; jC.ldadd = Hc;
            jC.C = h1b[s & 1]; jC.ldc = Hc; jC.act = 1; jC.valid = 1;
        }
        gemm3_kernel<256, 64, 64, 4, 4>
            <<<dim3(Hc / 64, Bc / 64, 3), 256>>>(jA, jB, jC);
    }

    // ---- decoder: 2 balanced K=1024 units per GEMM launch (P0/P1 pre-rotation) ----
    const float* d1prev = h1b[(Tc - 1) & 1];
    for (int s = 0; s < ML; s++) {
        float* d0cur = d0b[s & 1];
        float* d1cur = d1b[s & 1];
        {   // L1: d0_s = tanh(emb[tok]@Wih0 + P0 + b0);  P1 = d1_{s-1}@Whh1
            GemmJob jA = inv, jB = inv;
            jA.A = emb; jA.lda = Hc; jA.W = dWih0; jA.K = Hc;
            jA.gather = tok;
            jA.bias = db0; jA.addmat = P0; jA.ldadd = Hc;
            jA.C = d0cur; jA.ldc = Hc; jA.act = 1; jA.valid = 1;
            jB.A = d1prev; jB.lda = Hc; jB.W = dWhh1; jB.K = Hc;
            jB.C = P1; jB.ldc = Hc; jB.act = 0; jB.valid = 1;
            gemm3_kernel<256, 64, 64, 4, 4>
                <<<dim3(Hc / 64, Bc / 64, 2), 256>>>(jA, jB, inv);
        }
        {   // L2: d1_s = tanh(d0_s@Wih1 + P1 + b1);  P0 = d0_s@Whh0 (for s+1)
            GemmJob jA = inv, jB = inv;
            jA.A = d0cur; jA.lda = Hc; jA.W = dWih1; jA.K = Hc;
            jA.bias = db1; jA.addmat = P1; jA.ldadd = Hc;
            jA.C = d1cur; jA.ldc = Hc; jA.act = 1; jA.valid = 1;
            jB.A = d0cur; jB.lda = Hc; jB.W = dWhh0; jB.K = Hc;
            jB.C = P0; jB.ldc = Hc; jB.act = 0; jB.valid = 1;
            gemm3_kernel<256, 64, 64, 4, 4>
                <<<dim3(Hc / 64, Bc / 64, 2), 256>>>(jA, jB, inv);
        }
        logits_kernel<<<Bc, 256>>>(d1cur, fcW, fcb, out, s, tok);
        d1prev = d1cur;
    }

    copy_hidden_kernel<<<(Bc * Hc + 255) / 256, 256>>>(
        d0b[(ML - 1) & 1], d1b[(ML - 1) & 1], out + (size_t)Bc * Vc * ML);
}

// round 12
// speedup vs baseline: 1.6407x; 1.2216x over previous
#include <cuda_runtime.h>
#include <cstdint>
#include <cstddef>

// Problem dims
#define Bc 256
#define Tc 128
#define Hc 1024
#define Vc 64
#define Lc 457
#define ML 64
#define KSPLIT 4
#define BCHC ((size_t)Bc * Hc)

typedef unsigned long long ull;

// ---------------- device scratch (no allocs allowed) ----------------
__device__ float g_U0[(size_t)Bc * Tc * Hc];   // x @ enc_Wih0^T + b0
__device__ float g_h0[2][Bc * Hc];
__device__ float g_h1[2][Bc * Hc];
__device__ float g_V [2][Bc * Hc];             // h0_t @ eWih1^T + b1
__device__ float g_d0[2][Bc * Hc];
__device__ float g_d1[2][Bc * Hc];
__device__ float g_P0[Bc * Hc];                // d0_{s-1} @ dWhh0^T (pre-rotated)
__device__ float g_P1[Bc * Hc];                // d1_{s-1} @ dWhh1^T
__device__ float g_zero[Bc * Hc];
__device__ int   g_tok[Bc];
__device__ float g_SK[3 * KSPLIT * BCHC];      // split-K partial sums (12 MB)

// ---------------- packed fp32 helpers (sm_103a f32x2) ----------------
__device__ __forceinline__ ull dup2(float a) {
    ull r;
    asm("mov.b64 %0, {%1, %1};" : "=l"(r) : "r"(__float_as_uint(a)));
    return r;
}
__device__ __forceinline__ void ffma2(ull& d, ull a, ull b) {
    asm("fma.rn.f32x2 %0, %1, %2, %0;" : "+l"(d) : "l"(a), "l"(b));
}
__device__ __forceinline__ void unpk(ull v, float& lo, float& hi) {
    unsigned int a, b;
    asm("mov.b64 {%0, %1}, %2;" : "=r"(a), "=r"(b) : "l"(v));
    lo = __uint_as_float(a);
    hi = __uint_as_float(b);
}

// ---------------- job descriptors ----------------
struct GemmJob {
    const float* A; long lda; const float* W;  // C/part = A @ W^T (+ epilogue)
    int K;
    const int* gather;                          // optional row gather on A
    const float* bias; const float* addmat; long ldadd;
    float* C; long ldc;                         // direct mode output
    float* part;                                // split-K partial base (slot)
    int act; int valid;
};
struct EpiJob {
    const float* part;                          // KSPLIT partials, stride BCHC
    const float* bias; const float* addmat; long ldadd;
    float* C; long ldc; int act; int valid;
};

// ---------------- tile loaders (BR rows x 16 k-cols) ----------------
template<int NT, int BR>
__device__ __forceinline__ void load_tile(
    const float* __restrict__ A, long lda, const int* __restrict__ gather,
    int r_base, int K, int k0, int tid, float (&r)[BR * 4 / NT][4])
{
    constexpr int NC = BR * 4 / NT;
#pragma unroll
    for (int i = 0; i < NC; i++) {
        int cid = tid + i * NT;
        int row = cid >> 2, kq = cid & 3;
        int kk = k0 + kq * 4;
        long arow = gather ? (long)__ldg(&gather[r_base + row]) : (long)(r_base + row);
        const float* p = A + arow * lda + kk;
        if (kk + 3 < K && ((((uintptr_t)p) & 15u) == 0)) {
            float4 v = *(const float4*)p;
            r[i][0] = v.x; r[i][1] = v.y; r[i][2] = v.z; r[i][3] = v.w;
        } else {
#pragma unroll
            for (int j = 0; j < 4; j++)
                r[i][j] = (kk + j < K) ? __ldg(p + j) : 0.0f;
        }
    }
}

template<int NT, int BR>
__device__ __forceinline__ void store_tile(
    float (&S)[16][BR], int tid, const float (&r)[BR * 4 / NT][4])
{
    constexpr int NC = BR * 4 / NT;
#pragma unroll
    for (int i = 0; i < NC; i++) {
        int cid = tid + i * NT;
        int row = cid >> 2, kq = cid & 3;
#pragma unroll
        for (int j = 0; j < 4; j++)
            S[kq * 4 + j][row] = r[i][j];
    }
}

// ---------------- micro-kernel (R7-proven): TM x TN per thread via f32x2 ----------------
template<int BM, int BN, int TM, int TN>
__device__ __forceinline__ void mac_block(
    const float (&As)[16][BM], const float (&Ws)[16][BN],
    int r0, int c0, ull (&acc)[TM][TN / 2])
{
#pragma unroll
    for (int k = 0; k < 16; k++) {
        ull ad[TM];
#pragma unroll
        for (int i = 0; i < TM; i += 4) {
            float4 av = *(const float4*)&As[k][r0 + i];
            ad[i + 0] = dup2(av.x);
            ad[i + 1] = dup2(av.y);
            ad[i + 2] = dup2(av.z);
            ad[i + 3] = dup2(av.w);
        }
        ull wv[TN / 2];
#pragma unroll
        for (int p = 0; p < TN / 2; p += 2) {
            ulonglong2 w2 = *(const ulonglong2*)&Ws[k][c0 + 2 * p];
            wv[p] = w2.x;
            wv[p + 1] = w2.y;
        }
#pragma unroll
        for (int i = 0; i < TM; i++)
#pragma unroll
            for (int p = 0; p < TN / 2; p++)
                ffma2(acc[i][p], ad[i], wv[p]);
    }
}

// ---------------- K-staged double-buffered mainloop ----------------
// Kloop = #columns to process; lda_w = W row stride (full K for split mode)
template<int NT, int BM, int BN, int TM, int TN>
__device__ __forceinline__ void gemm_mainloop(
    const float* __restrict__ A, long lda,
    const float* __restrict__ W, long lda_w, int Kloop,
    const int* __restrict__ gather,
    int m0, int n0, int tid, int r0, int c0,
    float (&As)[2][16][BM], float (&Ws)[2][16][BN],
    ull (&acc)[TM][TN / 2])
{
    constexpr int NCA = BM * 4 / NT;
    constexpr int NCW = BN * 4 / NT;
    float ar[NCA][4], wr[NCW][4];
    int nkb = (Kloop + 15) / 16;

    load_tile<NT, BM>(A, lda, gather, m0, Kloop, 0, tid, ar);
    load_tile<NT, BN>(W, lda_w, nullptr, n0, Kloop, 0, tid, wr);
    store_tile<NT, BM>(As[0], tid, ar);
    store_tile<NT, BN>(Ws[0], tid, wr);
    __syncthreads();

    int buf = 0;
    for (int kb = 0; kb < nkb; kb++) {
        bool hn = (kb + 1 < nkb);
        if (hn) {
            load_tile<NT, BM>(A, lda, gather, m0, Kloop, (kb + 1) * 16, tid, ar);
            load_tile<NT, BN>(W, lda_w, nullptr, n0, Kloop, (kb + 1) * 16, tid, wr);
        }
        mac_block<BM, BN, TM, TN>(As[buf], Ws[buf], r0, c0, acc);
        if (hn) {
            store_tile<NT, BM>(As[buf ^ 1], tid, ar);
            store_tile<NT, BN>(Ws[buf ^ 1], tid, wr);
        }
        __syncthreads();
        buf ^= 1;
    }
}

// ---------------- direct GEMM kernel (precompute path) ----------------
template<int NT, int BM, int BN, int TM, int TN>
__global__ void __launch_bounds__(NT)
gemm3_kernel(GemmJob j0, GemmJob j1, GemmJob j2)
{
    GemmJob j = (blockIdx.z == 0) ? j0 : ((blockIdx.z == 1) ? j1 : j2);
    if (!j.valid) return;

    __shared__ float As[2][16][BM];
    __shared__ float Ws[2][16][BN];

    constexpr int CT = BN / TN;
    int tid = threadIdx.x;
    int m0 = blockIdx.y * BM;
    int n0 = blockIdx.x * BN;
    int ty = tid / CT, tx = tid % CT;
    int r0 = ty * TM, c0 = tx * TN;

    ull acc[TM][TN / 2] = {};
    gemm_mainloop<NT, BM, BN, TM, TN>(j.A, j.lda, j.W, (long)j.K, j.K, j.gather,
                                      m0, n0, tid, r0, c0, As, Ws, acc);

#pragma unroll
    for (int i = 0; i < TM; i++) {
        int m = m0 + r0 + i;
        float o[TN];
#pragma unroll
        for (int p = 0; p < TN / 2; p++)
            unpk(acc[i][p], o[2 * p], o[2 * p + 1]);
#pragma unroll
        for (int q = 0; q < TN; q++) {
            float v = o[q];
            int n = n0 + c0 + q;
            if (j.bias)   v += __ldg(&j.bias[n]);
            if (j.addmat) v += __ldg(&j.addmat[(long)m * j.ldadd + n]);
            if (j.act)    v = tanhf(v);
            o[q] = v;
        }
#pragma unroll
        for (int q = 0; q < TN; q += 4)
            *(float4*)&j.C[(long)m * j.ldc + n0 + c0 + q] = *(const float4*)&o[q];
    }
}

// ---------------- split-K GEMM kernel: raw partial sums to scratch ----------------
// blockIdx.z = job * KSPLIT + h; block computes columns [h*K/KS, (h+1)*K/KS)
template<int NT, int BM, int BN, int TM, int TN>
__global__ void __launch_bounds__(NT)
gemmsk_kernel(GemmJob j0, GemmJob j1, GemmJob j2)
{
    int job = blockIdx.z / KSPLIT;
    int h = blockIdx.z % KSPLIT;
    GemmJob j = (job == 0) ? j0 : ((job == 1) ? j1 : j2);
    if (!j.valid) return;

    __shared__ float As[2][16][BM];
    __shared__ float Ws[2][16][BN];

    constexpr int CT = BN / TN;
    int tid = threadIdx.x;
    int m0 = blockIdx.y * BM;
    int n0 = blockIdx.x * BN;
    int ty = tid / CT, tx = tid % CT;
    int r0 = ty * TM, c0 = tx * TN;

    int Kh = j.K / KSPLIT;
    const float* A = j.A + (long)h * Kh;   // column offset; rows via lda
    const float* W = j.W + (long)h * Kh;

    ull acc[TM][TN / 2] = {};
    gemm_mainloop<NT, BM, BN, TM, TN>(A, j.lda, W, (long)j.K, Kh, j.gather,
                                      m0, n0, tid, r0, c0, As, Ws, acc);

    float* P = j.part + (size_t)h * BCHC;
#pragma unroll
    for (int i = 0; i < TM; i++) {
        int m = m0 + r0 + i;
        float o[TN];
#pragma unroll
        for (int p = 0; p < TN / 2; p++)
            unpk(acc[i][p], o[2 * p], o[2 * p + 1]);
#pragma unroll
        for (int q = 0; q < TN; q += 4)
            *(float4*)&P[(size_t)m * Hc + n0 + c0 + q] = *(const float4*)&o[q];
    }
}

// ---------------- split-K epilogue: sum parts + bias + addmat + tanh ----------------
__global__ void __launch_bounds__(256)
epi_kernel(EpiJob e0, EpiJob e1, EpiJob e2)
{
    EpiJob e = (blockIdx.y == 0) ? e0 : ((blockIdx.y == 1) ? e1 : e2);
    if (!e.valid) return;

    size_t idx = ((size_t)blockIdx.x * 256 + threadIdx.x) * 4;
    int m = (int)(idx >> 10);          // / Hc
    int n = (int)(idx & (Hc - 1));     // % Hc

    float4 s = *(const float4*)&e.part[idx];
#pragma unroll
    for (int h = 1; h < KSPLIT; h++) {
        float4 p = *(const float4*)&e.part[(size_t)h * BCHC + idx];
        s.x += p.x; s.y += p.y; s.z += p.z; s.w += p.w;
    }
    if (e.bias) {
        float4 b = *(const float4*)&e.bias[n];
        s.x += b.x; s.y += b.y; s.z += b.z; s.w += b.w;
    }
    if (e.addmat) {
        float4 a = *(const float4*)&e.addmat[(long)m * e.ldadd + n];
        s.x += a.x; s.y += a.y; s.z += a.z; s.w += a.w;
    }
    if (e.act) {
        s.x = tanhf(s.x); s.y = tanhf(s.y); s.z = tanhf(s.z); s.w = tanhf(s.w);
    }
    *(float4*)&e.C[(long)m * e.ldc + n] = s;
}

// ---------------- logits + argmax (proven, one block per batch row) ----------------
__global__ void __launch_bounds__(256)
logits_kernel(const float* __restrict__ d1, const float* __restrict__ fcW,
              const float* __restrict__ fcb, float* __restrict__ out,
              int step, int* __restrict__ tok)
{
    __shared__ float hs[Hc];
    __shared__ float vals[Vc];
    int b = blockIdx.x, tid = threadIdx.x;

    *(float4*)&hs[tid * 4] = *(const float4*)&d1[(size_t)b * Hc + tid * 4];
    __syncthreads();

    int warp = tid >> 5, lane = tid & 31;
#pragma unroll
    for (int j = 0; j < 8; j++) {
        int v = warp * 8 + j;
        const float4* wp = (const float4*)&fcW[(size_t)v * Hc];
        float s = 0.0f;
#pragma unroll
        for (int i = 0; i < 8; i++) {
            float4 w4 = __ldg(&wp[lane + i * 32]);
            float4 h4 = *(const float4*)&hs[(lane + i * 32) * 4];
            s += w4.x * h4.x + w4.y * h4.y + w4.z * h4.z + w4.w * h4.w;
        }
#pragma unroll
        for (int o = 16; o; o >>= 1) s += __shfl_xor_sync(0xffffffffu, s, o);
        if (lane == 0) {
            s += fcb[v];
            vals[v] = s;
            out[((size_t)b * Vc + (size_t)v) * ML + (size_t)step] = s;
        }
    }
    __syncthreads();
    if (tid == 0) {
        float best = vals[0]; int bi = 0;
#pragma unroll
        for (int i = 1; i < Vc; i++)
            if (vals[i] > best) { best = vals[i]; bi = i; }   // first-max = jnp.argmax
        tok[b] = bi;
    }
}

__global__ void init_kernel(float* __restrict__ z, int* __restrict__ tok)
{
    int i = blockIdx.x * blockDim.x + threadIdx.x;
    if (i < Bc * Hc) z[i] = 0.0f;
    if (i < Bc) tok[i] = 0;
}

__global__ void copy_hidden_kernel(const float* __restrict__ d0,
                                   const float* __restrict__ d1,
                                   float* __restrict__ o)
{
    int i = blockIdx.x * blockDim.x + threadIdx.x;
    if (i < Bc * Hc) {
        o[i] = d0[i];
        o[Bc * Hc + i] = d1[i];
    }
}

// ---------------- host ----------------
extern "C" void kernel_launch(void* const* d_in, const int* in_sizes, int n_in,
                              void* d_out, int out_size)
{
    (void)in_sizes; (void)n_in; (void)out_size;
    const float* x     = (const float*)d_in[0];
    const float* emb   = (const float*)d_in[1];
    const float* eWih0 = (const float*)d_in[2];
    const float* eWhh0 = (const float*)d_in[3];
    const float* eb0   = (const float*)d_in[4];
    const float* eWih1 = (const float*)d_in[5];
    const float* eWhh1 = (const float*)d_in[6];
    const float* eb1   = (const float*)d_in[7];
    const float* dWih0 = (const float*)d_in[8];
    const float* dWhh0 = (const float*)d_in[9];
    const float* db0   = (const float*)d_in[10];
    const float* dWih1 = (const float*)d_in[11];
    const float* dWhh1 = (const float*)d_in[12];
    const float* db1   = (const float*)d_in[13];
    const float* fcW   = (const float*)d_in[14];
    const float* fcb   = (const float*)d_in[15];
    float* out = (float*)d_out;

    float *U0, *h0base, *h1base, *Vbase, *d0base, *d1base, *P0, *P1, *zero, *SK;
    int* tok;
    cudaGetSymbolAddress((void**)&U0, g_U0);
    cudaGetSymbolAddress((void**)&h0base, g_h0);
    cudaGetSymbolAddress((void**)&h1base, g_h1);
    cudaGetSymbolAddress((void**)&Vbase, g_V);
    cudaGetSymbolAddress((void**)&d0base, g_d0);
    cudaGetSymbolAddress((void**)&d1base, g_d1);
    cudaGetSymbolAddress((void**)&P0, g_P0);
    cudaGetSymbolAddress((void**)&P1, g_P1);
    cudaGetSymbolAddress((void**)&zero, g_zero);
    cudaGetSymbolAddress((void**)&tok, g_tok);
    cudaGetSymbolAddress((void**)&SK, g_SK);

    float* h0b[2] = { h0base, h0base + BCHC };
    float* h1b[2] = { h1base, h1base + BCHC };
    float* Vb[2]  = { Vbase,  Vbase  + BCHC };
    float* d0b[2] = { d0base, d0base + BCHC };
    float* d1b[2] = { d1base, d1base + BCHC };
    float* SKs[3] = { SK, SK + KSPLIT * BCHC, SK + 2 * KSPLIT * BCHC };

    init_kernel<<<(Bc * Hc + 255) / 256, 256>>>(zero, tok);

    GemmJob inv = {}; inv.valid = 0;
    EpiJob einv = {}; einv.valid = 0;

    // ---- precompute U0 = x_flat @ eWih0^T + b0 (direct path) ----
    {
        GemmJob j = {};
        j.A = x; j.lda = Lc; j.W = eWih0; j.K = Lc;
        j.bias = eb0;
        j.C = U0; j.ldc = Hc; j.act = 0; j.valid = 1;
        gemm3_kernel<256, 128, 64, 8, 4>
            <<<dim3(Hc / 64, (Bc * Tc) / 128, 1), 256>>>(j, inv, inv);
    }

    dim3 grid_epi(Bc * Hc / (256 * 4), 3);   // (256, 3)

    // ---- encoder: 3 balanced split-K units per launch (skewed chain) ----
    // launch t: A) h0_t = tanh(h0_{t-1}@Whh0 + U0[:,t])
    //           B) V_{t-1} = h0_{t-1}@Wih1 + b1
    //           C) h1_{t-2} = tanh(h1_{t-3}@Whh1 + V_{t-2})
    // t == Tc: slot A computes decoder bootstrap P0 = h0_final @ dWhh0
    for (int t = 0; t <= Tc + 1; t++) {
        GemmJob jA = inv, jB = inv, jC = inv;
        EpiJob eA = einv, eB = einv, eC = einv;
        if (t < Tc) {
            jA.A = (t == 0) ? zero : h0b[(t - 1) & 1];
            jA.lda = Hc; jA.W = eWhh0; jA.K = Hc;
            jA.part = SKs[0]; jA.valid = 1;
            eA.part = SKs[0]; eA.addmat = U0 + (size_t)t * Hc; eA.ldadd = (long)Tc * Hc;
            eA.C = h0b[t & 1]; eA.ldc = Hc; eA.act = 1; eA.valid = 1;
        } else if (t == Tc) {
            jA.A = h0b[(Tc - 1) & 1]; jA.lda = Hc; jA.W = dWhh0; jA.K = Hc;
            jA.part = SKs[0]; jA.valid = 1;
            eA.part = SKs[0]; eA.C = P0; eA.ldc = Hc; eA.act = 0; eA.valid = 1;
        }
        if (t >= 1 && t <= Tc) {
            int s = t - 1;
            jB.A = h0b[s & 1]; jB.lda = Hc; jB.W = eWih1; jB.K = Hc;
            jB.part = SKs[1]; jB.valid = 1;
            eB.part = SKs[1]; eB.bias = eb1;
            eB.C = Vb[s & 1]; eB.ldc = Hc; eB.act = 0; eB.valid = 1;
        }
        if (t >= 2) {
            int s = t - 2;
            jC.A = (s == 0) ? zero : h1b[(s - 1) & 1];
            jC.lda = Hc; jC.W = eWhh1; jC.K = Hc;
            jC.part = SKs[2]; jC.valid = 1;
            eC.part = SKs[2]; eC.addmat = Vb[s & 1]; eC.ldadd = Hc;
            eC.C = h1b[s & 1]; eC.ldc = Hc; eC.act = 1; eC.valid = 1;
        }
        gemmsk_kernel<256, 64, 64, 4, 4>
            <<<dim3(Hc / 64, Bc / 64, 3 * KSPLIT), 256>>>(jA, jB, jC);
        epi_kernel<<<grid_epi, 256>>>(eA, eB, eC);
    }

    // ---- decoder: 2 balanced split-K units per GEMM launch (P0/P1 pre-rotation) ----
    const float* d1prev = h1b[(Tc - 1) & 1];
    for (int s = 0; s < ML; s++) {
        float* d0cur = d0b[s & 1];
        float* d1cur = d1b[s & 1];
        {   // L1: d0_s = tanh(emb[tok]@Wih0 + P0 + b0);  P1 = d1_{s-1}@Whh1
            GemmJob jA = inv, jB = inv;
            EpiJob eA = einv, eB = einv;
            jA.A = emb; jA.lda = Hc; jA.W = dWih0; jA.K = Hc;
            jA.gather = tok; jA.part = SKs[0]; jA.valid = 1;
            eA.part = SKs[0]; eA.bias = db0; eA.addmat = P0; eA.ldadd = Hc;
            eA.C = d0cur; eA.ldc = Hc; eA.act = 1; eA.valid = 1;
            jB.A = d1prev; jB.lda = Hc; jB.W = dWhh1; jB.K = Hc;
            jB.part = SKs[1]; jB.valid = 1;
            eB.part = SKs[1]; eB.C = P1; eB.ldc = Hc; eB.act = 0; eB.valid = 1;
            gemmsk_kernel<256, 64, 64, 4, 4>
                <<<dim3(Hc / 64, Bc / 64, 2 * KSPLIT), 256>>>(jA, jB, inv);
            epi_kernel<<<dim3(Bc * Hc / 1024, 2), 256>>>(eA, eB, einv);
        }
        {   // L2: d1_s = tanh(d0_s@Wih1 + P1 + b1);  P0 = d0_s@Whh0 (for s+1)
            GemmJob jA = inv, jB = inv;
            EpiJob eA = einv, eB = einv;
            jA.A = d0cur; jA.lda = Hc; jA.W = dWih1; jA.K = Hc;
            jA.part = SKs[0]; jA.valid = 1;
            eA.part = SKs[0]; eA.bias = db1; eA.addmat = P1; eA.ldadd = Hc;
            eA.C = d1cur; eA.ldc = Hc; eA.act = 1; eA.valid = 1;
            jB.A = d0cur; jB.lda = Hc; jB.W = dWhh0; jB.K = Hc;
            jB.part = SKs[1]; jB.valid = 1;
            eB.part = SKs[1]; eB.C = P0; eB.ldc = Hc; eB.act = 0; eB.valid = 1;
            gemmsk_kernel<256, 64, 64, 4, 4>
                <<<dim3(Hc / 64, Bc / 64, 2 * KSPLIT), 256>>>(jA, jB, inv);
            epi_kernel<<<dim3(Bc * Hc / 1024, 2), 256>>>(eA, eB, einv);
        }
        logits_kernel<<<Bc, 256>>>(d1cur, fcW, fcb, out, s, tok);
        d1prev = d1cur;
    }

    copy_hidden_kernel<<<(Bc * Hc + 255) / 256, 256>>>(
        d0b[(ML - 1) & 1], d1b[(ML - 1) & 1], out + (size_t)Bc * Vc * ML);
}

// round 14
// speedup vs baseline: 1.7482x; 1.0655x over previous
#include <cuda_runtime.h>
#include <cstdint>
#include <cstddef>

// Problem dims
#define Bc 256
#define Tc 128
#define Hc 1024
#define Vc 64
#define Lc 457
#define ML 64
#define KSPLIT 8
#define BCHC ((size_t)Bc * Hc)

typedef unsigned long long ull;

// ---------------- device scratch (no allocs allowed) ----------------
__device__ float g_U0[(size_t)Bc * Tc * Hc];   // x @ enc_Wih0^T + b0
__device__ float g_h0[2][Bc * Hc];
__device__ float g_h1[2][Bc * Hc];
__device__ float g_V [2][Bc * Hc];             // h0_t @ eWih1^T + b1
__device__ float g_d0[2][Bc * Hc];
__device__ float g_d1[2][Bc * Hc];
__device__ float g_P0[Bc * Hc];                // d0_{s-1} @ dWhh0^T (pre-rotated)
__device__ float g_P1[Bc * Hc];                // d1_{s-1} @ dWhh1^T
__device__ float g_zero[Bc * Hc];
__device__ int   g_tok[Bc];
__device__ float g_SK[3 * KSPLIT * BCHC];      // split-K partial sums (24 MB)

// ---------------- packed fp32 helpers (sm_103a f32x2) ----------------
__device__ __forceinline__ ull dup2(float a) {
    ull r;
    asm("mov.b64 %0, {%1, %1};" : "=l"(r) : "r"(__float_as_uint(a)));
    return r;
}
__device__ __forceinline__ void ffma2(ull& d, ull a, ull b) {
    asm("fma.rn.f32x2 %0, %1, %2, %0;" : "+l"(d) : "l"(a), "l"(b));
}
__device__ __forceinline__ void unpk(ull v, float& lo, float& hi) {
    unsigned int a, b;
    asm("mov.b64 {%0, %1}, %2;" : "=r"(a), "=r"(b) : "l"(v));
    lo = __uint_as_float(a);
    hi = __uint_as_float(b);
}

// ---------------- job descriptors ----------------
struct GemmJob {
    const float* A; long lda; const float* W;  // C/part = A @ W^T (+ epilogue)
    int K;
    const int* gather;                          // optional row gather on A
    const float* bias; const float* addmat; long ldadd;
    float* C; long ldc;                         // direct mode output
    float* part;                                // split-K partial base (slot)
    int act; int valid;
};
struct EpiJob {
    const float* part;                          // KSPLIT partials, stride BCHC
    const float* bias; const float* addmat; long ldadd;
    float* C; long ldc; int act; int valid;
};

// ---------------- tile loaders (BR rows x 16 k-cols) ----------------
template<int NT, int BR>
__device__ __forceinline__ void load_tile(
    const float* __restrict__ A, long lda, const int* __restrict__ gather,
    int r_base, int K, int k0, int tid, float (&r)[BR * 4 / NT][4])
{
    constexpr int NC = BR * 4 / NT;
#pragma unroll
    for (int i = 0; i < NC; i++) {
        int cid = tid + i * NT;
        int row = cid >> 2, kq = cid & 3;
        int kk = k0 + kq * 4;
        long arow = gather ? (long)__ldg(&gather[r_base + row]) : (long)(r_base + row);
        const float* p = A + arow * lda + kk;
        if (kk + 3 < K && ((((uintptr_t)p) & 15u) == 0)) {
            float4 v = *(const float4*)p;
            r[i][0] = v.x; r[i][1] = v.y; r[i][2] = v.z; r[i][3] = v.w;
        } else {
#pragma unroll
            for (int j = 0; j < 4; j++)
                r[i][j] = (kk + j < K) ? __ldg(p + j) : 0.0f;
        }
    }
}

template<int NT, int BR>
__device__ __forceinline__ void store_tile(
    float (&S)[16][BR], int tid, const float (&r)[BR * 4 / NT][4])
{
    constexpr int NC = BR * 4 / NT;
#pragma unroll
    for (int i = 0; i < NC; i++) {
        int cid = tid + i * NT;
        int row = cid >> 2, kq = cid & 3;
#pragma unroll
        for (int j = 0; j < 4; j++)
            S[kq * 4 + j][row] = r[i][j];
    }
}

// ---------------- micro-kernel (R7-proven): TM x TN per thread via f32x2 ----------------
template<int BM, int BN, int TM, int TN>
__device__ __forceinline__ void mac_block(
    const float (&As)[16][BM], const float (&Ws)[16][BN],
    int r0, int c0, ull (&acc)[TM][TN / 2])
{
#pragma unroll
    for (int k = 0; k < 16; k++) {
        ull ad[TM];
#pragma unroll
        for (int i = 0; i < TM; i += 4) {
            float4 av = *(const float4*)&As[k][r0 + i];
            ad[i + 0] = dup2(av.x);
            ad[i + 1] = dup2(av.y);
            ad[i + 2] = dup2(av.z);
            ad[i + 3] = dup2(av.w);
        }
        ull wv[TN / 2];
#pragma unroll
        for (int p = 0; p < TN / 2; p += 2) {
            ulonglong2 w2 = *(const ulonglong2*)&Ws[k][c0 + 2 * p];
            wv[p] = w2.x;
            wv[p + 1] = w2.y;
        }
#pragma unroll
        for (int i = 0; i < TM; i++)
#pragma unroll
            for (int p = 0; p < TN / 2; p++)
                ffma2(acc[i][p], ad[i], wv[p]);
    }
}

// ---------------- K-staged double-buffered mainloop ----------------
// Kloop = #columns to process; lda_w = W row stride (full K for split mode)
template<int NT, int BM, int BN, int TM, int TN>
__device__ __forceinline__ void gemm_mainloop(
    const float* __restrict__ A, long lda,
    const float* __restrict__ W, long lda_w, int Kloop,
    const int* __restrict__ gather,
    int m0, int n0, int tid, int r0, int c0,
    float (&As)[2][16][BM], float (&Ws)[2][16][BN],
    ull (&acc)[TM][TN / 2])
{
    constexpr int NCA = BM * 4 / NT;
    constexpr int NCW = BN * 4 / NT;
    float ar[NCA][4], wr[NCW][4];
    int nkb = (Kloop + 15) / 16;

    load_tile<NT, BM>(A, lda, gather, m0, Kloop, 0, tid, ar);
    load_tile<NT, BN>(W, lda_w, nullptr, n0, Kloop, 0, tid, wr);
    store_tile<NT, BM>(As[0], tid, ar);
    store_tile<NT, BN>(Ws[0], tid, wr);
    __syncthreads();

    int buf = 0;
    for (int kb = 0; kb < nkb; kb++) {
        bool hn = (kb + 1 < nkb);
        if (hn) {
            load_tile<NT, BM>(A, lda, gather, m0, Kloop, (kb + 1) * 16, tid, ar);
            load_tile<NT, BN>(W, lda_w, nullptr, n0, Kloop, (kb + 1) * 16, tid, wr);
        }
        mac_block<BM, BN, TM, TN>(As[buf], Ws[buf], r0, c0, acc);
        if (hn) {
            store_tile<NT, BM>(As[buf ^ 1], tid, ar);
            store_tile<NT, BN>(Ws[buf ^ 1], tid, wr);
        }
        __syncthreads();
        buf ^= 1;
    }
}

// ---------------- direct GEMM kernel (precompute path) ----------------
template<int NT, int BM, int BN, int TM, int TN>
__global__ void __launch_bounds__(NT)
gemm3_kernel(GemmJob j0, GemmJob j1, GemmJob j2)
{
    GemmJob j = (blockIdx.z == 0) ? j0 : ((blockIdx.z == 1) ? j1 : j2);
    if (!j.valid) return;

    __shared__ float As[2][16][BM];
    __shared__ float Ws[2][16][BN];

    constexpr int CT = BN / TN;
    int tid = threadIdx.x;
    int m0 = blockIdx.y * BM;
    int n0 = blockIdx.x * BN;
    int ty = tid / CT, tx = tid % CT;
    int r0 = ty * TM, c0 = tx * TN;

    ull acc[TM][TN / 2] = {};
    gemm_mainloop<NT, BM, BN, TM, TN>(j.A, j.lda, j.W, (long)j.K, j.K, j.gather,
                                      m0, n0, tid, r0, c0, As, Ws, acc);

#pragma unroll
    for (int i = 0; i < TM; i++) {
        int m = m0 + r0 + i;
        float o[TN];
#pragma unroll
        for (int p = 0; p < TN / 2; p++)
            unpk(acc[i][p], o[2 * p], o[2 * p + 1]);
#pragma unroll
        for (int q = 0; q < TN; q++) {
            float v = o[q];
            int n = n0 + c0 + q;
            if (j.bias)   v += __ldg(&j.bias[n]);
            if (j.addmat) v += __ldg(&j.addmat[(long)m * j.ldadd + n]);
            if (j.act)    v = tanhf(v);
            o[q] = v;
        }
#pragma unroll
        for (int q = 0; q < TN; q += 4)
            *(float4*)&j.C[(long)m * j.ldc + n0 + c0 + q] = *(const float4*)&o[q];
    }
}

// ---------------- split-K GEMM kernel: raw partial sums to scratch ----------------
// blockIdx.z = job * KSPLIT + h; block computes columns [h*K/KS, (h+1)*K/KS)
template<int NT, int BM, int BN, int TM, int TN>
__global__ void __launch_bounds__(NT)
gemmsk_kernel(GemmJob j0, GemmJob j1, GemmJob j2)
{
    int job = blockIdx.z / KSPLIT;
    int h = blockIdx.z % KSPLIT;
    GemmJob j = (job == 0) ? j0 : ((job == 1) ? j1 : j2);
    if (!j.valid) return;

    __shared__ float As[2][16][BM];
    __shared__ float Ws[2][16][BN];

    constexpr int CT = BN / TN;
    int tid = threadIdx.x;
    int m0 = blockIdx.y * BM;
    int n0 = blockIdx.x * BN;
    int ty = tid / CT, tx = tid % CT;
    int r0 = ty * TM, c0 = tx * TN;

    int Kh = j.K / KSPLIT;
    const float* A = j.A + (long)h * Kh;   // column offset; rows via lda
    const float* W = j.W + (long)h * Kh;

    ull acc[TM][TN / 2] = {};
    gemm_mainloop<NT, BM, BN, TM, TN>(A, j.lda, W, (long)j.K, Kh, j.gather,
                                      m0, n0, tid, r0, c0, As, Ws, acc);

    float* P = j.part + (size_t)h * BCHC;
#pragma unroll
    for (int i = 0; i < TM; i++) {
        int m = m0 + r0 + i;
        float o[TN];
#pragma unroll
        for (int p = 0; p < TN / 2; p++)
            unpk(acc[i][p], o[2 * p], o[2 * p + 1]);
#pragma unroll
        for (int q = 0; q < TN; q += 4)
            *(float4*)&P[(size_t)m * Hc + n0 + c0 + q] = *(const float4*)&o[q];
    }
}

// ---------------- epilogue value: sum KSPLIT parts + bias + addmat (+tanh) ----------------
__device__ __forceinline__ float4 epi_value(const EpiJob& e, size_t idx, int m, int n)
{
    float4 s = *(const float4*)&e.part[idx];
#pragma unroll
    for (int h = 1; h < KSPLIT; h++) {
        float4 p = *(const float4*)&e.part[(size_t)h * BCHC + idx];
        s.x += p.x; s.y += p.y; s.z += p.z; s.w += p.w;
    }
    if (e.bias) {
        float4 b = *(const float4*)&e.bias[n];
        s.x += b.x; s.y += b.y; s.z += b.z; s.w += b.w;
    }
    if (e.addmat) {
        float4 a = *(const float4*)&e.addmat[(long)m * e.ldadd + n];
        s.x += a.x; s.y += a.y; s.z += a.z; s.w += a.w;
    }
    if (e.act) {
        s.x = tanhf(s.x); s.y = tanhf(s.y); s.z = tanhf(s.z); s.w = tanhf(s.w);
    }
    return s;
}

// ---------------- split-K epilogue (up to 3 jobs) ----------------
__global__ void __launch_bounds__(256)
epi_kernel(EpiJob e0, EpiJob e1, EpiJob e2)
{
    EpiJob e = (blockIdx.y == 0) ? e0 : ((blockIdx.y == 1) ? e1 : e2);
    if (!e.valid) return;

    size_t idx = ((size_t)blockIdx.x * 256 + threadIdx.x) * 4;
    int m = (int)(idx >> 10);          // / Hc
    int n = (int)(idx & (Hc - 1));     // % Hc
    float4 s = epi_value(e, idx, m, n);
    *(float4*)&e.C[(long)m * e.ldc + n] = s;
}

// ---------------- decoder L2 epilogue FUSED with logits+argmax ----------------
// blockIdx.y == 0: job d1 -- one block = one batch row b; after writing d1,
//                  compute logits[b,:] and tok[b] in the same block.
// blockIdx.y == 1: job P0 (plain epilogue).
__global__ void __launch_bounds__(256)
epi_logits_kernel(EpiJob e0, EpiJob e1,
                  const float* __restrict__ fcW, const float* __restrict__ fcb,
                  float* __restrict__ out, int step, int* __restrict__ tok)
{
    __shared__ float hs[Hc];
    __shared__ float vals[Vc];

    EpiJob e = (blockIdx.y == 0) ? e0 : e1;
    int b = blockIdx.x, tid = threadIdx.x;
    size_t idx = ((size_t)b << 10) + (size_t)tid * 4;   // row b, cols tid*4..
    int n = tid * 4;

    float4 s = epi_value(e, idx, b, n);
    *(float4*)&e.C[(long)b * e.ldc + n] = s;

    if (blockIdx.y != 0) return;

    // logits tail: hs = d1[b,:]
    *(float4*)&hs[n] = s;
    __syncthreads();

    int warp = tid >> 5, lane = tid & 31;
#pragma unroll
    for (int j = 0; j < 8; j++) {
        int v = warp * 8 + j;
        const float4* wp = (const float4*)&fcW[(size_t)v * Hc];
        float sum = 0.0f;
#pragma unroll
        for (int i = 0; i < 8; i++) {
            float4 w4 = __ldg(&wp[lane + i * 32]);
            float4 h4 = *(const float4*)&hs[(lane + i * 32) * 4];
            sum += w4.x * h4.x + w4.y * h4.y + w4.z * h4.z + w4.w * h4.w;
        }
#pragma unroll
        for (int o = 16; o; o >>= 1) sum += __shfl_xor_sync(0xffffffffu, sum, o);
        if (lane == 0) {
            sum += fcb[v];
            vals[v] = sum;
            out[((size_t)b * Vc + (size_t)v) * ML + (size_t)step] = sum;
        }
    }
    __syncthreads();
    if (tid == 0) {
        float best = vals[0]; int bi = 0;
#pragma unroll
        for (int i = 1; i < Vc; i++)
            if (vals[i] > best) { best = vals[i]; bi = i; }   // first-max = jnp.argmax
        tok[b] = bi;
    }
}

__global__ void init_kernel(float* __restrict__ z, int* __restrict__ tok)
{
    int i = blockIdx.x * blockDim.x + threadIdx.x;
    if (i < Bc * Hc) z[i] = 0.0f;
    if (i < Bc) tok[i] = 0;
}

__global__ void copy_hidden_kernel(const float* __restrict__ d0,
                                   const float* __restrict__ d1,
                                   float* __restrict__ o)
{
    int i = blockIdx.x * blockDim.x + threadIdx.x;
    if (i < Bc * Hc) {
        o[i] = d0[i];
        o[Bc * Hc + i] = d1[i];
    }
}

// ---------------- host ----------------
extern "C" void kernel_launch(void* const* d_in, const int* in_sizes, int n_in,
                              void* d_out, int out_size)
{
    (void)in_sizes; (void)n_in; (void)out_size;
    const float* x     = (const float*)d_in[0];
    const float* emb   = (const float*)d_in[1];
    const float* eWih0 = (const float*)d_in[2];
    const float* eWhh0 = (const float*)d_in[3];
    const float* eb0   = (const float*)d_in[4];
    const float* eWih1 = (const float*)d_in[5];
    const float* eWhh1 = (const float*)d_in[6];
    const float* eb1   = (const float*)d_in[7];
    const float* dWih0 = (const float*)d_in[8];
    const float* dWhh0 = (const float*)d_in[9];
    const float* db0   = (const float*)d_in[10];
    const float* dWih1 = (const float*)d_in[11];
    const float* dWhh1 = (const float*)d_in[12];
    const float* db1   = (const float*)d_in[13];
    const float* fcW   = (const float*)d_in[14];
    const float* fcb   = (const float*)d_in[15];
    float* out = (float*)d_out;

    float *U0, *h0base, *h1base, *Vbase, *d0base, *d1base, *P0, *P1, *zero, *SK;
    int* tok;
    cudaGetSymbolAddress((void**)&U0, g_U0);
    cudaGetSymbolAddress((void**)&h0base, g_h0);
    cudaGetSymbolAddress((void**)&h1base, g_h1);
    cudaGetSymbolAddress((void**)&Vbase, g_V);
    cudaGetSymbolAddress((void**)&d0base, g_d0);
    cudaGetSymbolAddress((void**)&d1base, g_d1);
    cudaGetSymbolAddress((void**)&P0, g_P0);
    cudaGetSymbolAddress((void**)&P1, g_P1);
    cudaGetSymbolAddress((void**)&zero, g_zero);
    cudaGetSymbolAddress((void**)&tok, g_tok);
    cudaGetSymbolAddress((void**)&SK, g_SK);

    float* h0b[2] = { h0base, h0base + BCHC };
    float* h1b[2] = { h1base, h1base + BCHC };
    float* Vb[2]  = { Vbase,  Vbase  + BCHC };
    float* d0b[2] = { d0base, d0base + BCHC };
    float* d1b[2] = { d1base, d1base + BCHC };
    float* SKs[3] = { SK, SK + KSPLIT * BCHC, SK + 2 * KSPLIT * BCHC };

    init_kernel<<<(Bc * Hc + 255) / 256, 256>>>(zero, tok);

    GemmJob inv = {}; inv.valid = 0;
    EpiJob einv = {}; einv.valid = 0;

    // ---- precompute U0 = x_flat @ eWih0^T + b0 (direct path) ----
    {
        GemmJob j = {};
        j.A = x; j.lda = Lc; j.W = eWih0; j.K = Lc;
        j.bias = eb0;
        j.C = U0; j.ldc = Hc; j.act = 0; j.valid = 1;
        gemm3_kernel<256, 128, 64, 8, 4>
            <<<dim3(Hc / 64, (Bc * Tc) / 128, 1), 256>>>(j, inv, inv);
    }

    dim3 grid_epi3(Bc, 3);   // one block = one (job, batch-row)

    // ---- encoder: 3 balanced split-K units per launch (skewed chain) ----
    // launch t: A) h0_t = tanh(h0_{t-1}@Whh0 + U0[:,t])
    //           B) V_{t-1} = h0_{t-1}@Wih1 + b1
    //           C) h1_{t-2} = tanh(h1_{t-3}@Whh1 + V_{t-2})
    // t == Tc: slot A computes decoder bootstrap P0 = h0_final @ dWhh0
    for (int t = 0; t <= Tc + 1; t++) {
        GemmJob jA = inv, jB = inv, jC = inv;
        EpiJob eA = einv, eB = einv, eC = einv;
        if (t < Tc) {
            jA.A = (t == 0) ? zero : h0b[(t - 1) & 1];
            jA.lda = Hc; jA.W = eWhh0; jA.K = Hc;
            jA.part = SKs[0]; jA.valid = 1;
            eA.part = SKs[0]; eA.addmat = U0 + (size_t)t * Hc; eA.ldadd = (long)Tc * Hc;
            eA.C = h0b[t & 1]; eA.ldc = Hc; eA.act = 1; eA.valid = 1;
        } else if (t == Tc) {
            jA.A = h0b[(Tc - 1) & 1]; jA.lda = Hc; jA.W = dWhh0; jA.K = Hc;
            jA.part = SKs[0]; jA.valid = 1;
            eA.part = SKs[0]; eA.C = P0; eA.ldc = Hc; eA.act = 0; eA.valid = 1;
        }
        if (t >= 1 && t <= Tc) {
            int s = t - 1;
            jB.A = h0b[s & 1]; jB.lda = Hc; jB.W = eWih1; jB.K = Hc;
            jB.part = SKs[1]; jB.valid = 1;
            eB.part = SKs[1]; eB.bias = eb1;
            eB.C = Vb[s & 1]; eB.ldc = Hc; eB.act = 0; eB.valid = 1;
        }
        if (t >= 2) {
            int s = t - 2;
            jC.A = (s == 0) ? zero : h1b[(s - 1) & 1];
            jC.lda = Hc; jC.W = eWhh1; jC.K = Hc;
            jC.part = SKs[2]; jC.valid = 1;
            eC.part = SKs[2]; eC.addmat = Vb[s & 1]; eC.ldadd = Hc;
            eC.C = h1b[s & 1]; eC.ldc = Hc; eC.act = 1; eC.valid = 1;
        }
        gemmsk_kernel<256, 64, 64, 4, 4>
            <<<dim3(Hc / 64, Bc / 64, 3 * KSPLIT), 256>>>(jA, jB, jC);
        epi_kernel<<<grid_epi3, 256>>>(eA, eB, eC);
    }

    // ---- decoder: 2 balanced split-K units per GEMM launch (P0/P1 pre-rotation) ----
    const float* d1prev = h1b[(Tc - 1) & 1];
    for (int s = 0; s < ML; s++) {
        float* d0cur = d0b[s & 1];
        float* d1cur = d1b[s & 1];
        {   // L1: d0_s = tanh(emb[tok]@Wih0 + P0 + b0);  P1 = d1_{s-1}@Whh1
            GemmJob jA = inv, jB = inv;
            EpiJob eA = einv, eB = einv;
            jA.A = emb; jA.lda = Hc; jA.W = dWih0; jA.K = Hc;
            jA.gather = tok; jA.part = SKs[0]; jA.valid = 1;
            eA.part = SKs[0]; eA.bias = db0; eA.addmat = P0; eA.ldadd = Hc;
            eA.C = d0cur; eA.ldc = Hc; eA.act = 1; eA.valid = 1;
            jB.A = d1prev; jB.lda = Hc; jB.W = dWhh1; jB.K = Hc;
            jB.part = SKs[1]; jB.valid = 1;
            eB.part = SKs[1]; eB.C = P1; eB.ldc = Hc; eB.act = 0; eB.valid = 1;
            gemmsk_kernel<256, 64, 64, 4, 4>
                <<<dim3(Hc / 64, Bc / 64, 2 * KSPLIT), 256>>>(jA, jB, inv);
            epi_kernel<<<dim3(Bc, 2), 256>>>(eA, eB, einv);
        }
        {   // L2: d1_s = tanh(d0_s@Wih1 + P1 + b1)  [+ fused logits/argmax];
            // P0 = d0_s@Whh0 (for s+1)
            GemmJob jA = inv, jB = inv;
            EpiJob eA = einv, eB = einv;
            jA.A = d0cur; jA.lda = Hc; jA.W = dWih1; jA.K = Hc;
            jA.part = SKs[0]; jA.valid = 1;
            eA.part = SKs[0]; eA.bias = db1; eA.addmat = P1; eA.ldadd = Hc;
            eA.C = d1cur; eA.ldc = Hc; eA.act = 1; eA.valid = 1;
            jB.A = d0cur; jB.lda = Hc; jB.W = dWhh0; jB.K = Hc;
            jB.part = SKs[1]; jB.valid = 1;
            eB.part = SKs[1]; eB.C = P0; eB.ldc = Hc; eB.act = 0; eB.valid = 1;
            gemmsk_kernel<256, 64, 64, 4, 4>
                <<<dim3(Hc / 64, Bc / 64, 2 * KSPLIT), 256>>>(jA, jB, inv);
            epi_logits_kernel<<<dim3(Bc, 2), 256>>>(eA, eB, fcW, fcb, out, s, tok);
        }
        d1prev = d1b[s & 1];
    }

    copy_hidden_kernel<<<(Bc * Hc + 255) / 256, 256>>>(
        d0b[(ML - 1) & 1], d1b[(ML - 1) & 1], out + (size_t)Bc * Vc * ML);
}

// round 17
// speedup vs baseline: 1.8801x; 1.0755x over previous
#include <cuda_runtime.h>
#include <cstdint>
#include <cstddef>

// Problem dims
#define Bc 256
#define Tc 128
#define Hc 1024
#define Vc 64
#define Lc 457
#define ML 64
#define KSPLIT 8
#define BCHC ((size_t)Bc * Hc)

typedef unsigned long long ull;

// ---------------- device scratch (no allocs allowed) ----------------
__device__ float g_U0[(size_t)Bc * Tc * Hc];   // x @ enc_Wih0^T + b0
__device__ float g_h0[2][Bc * Hc];
__device__ float g_h1[2][Bc * Hc];
__device__ float g_V [2][Bc * Hc];             // h0_t @ eWih1^T + b1
__device__ float g_d0[2][Bc * Hc];
__device__ float g_d1[2][Bc * Hc];
__device__ float g_P0[Bc * Hc];                // d0_{s-1} @ dWhh0^T (pre-rotated)
__device__ float g_P1[Bc * Hc];                // d1_{s-1} @ dWhh1^T
__device__ float g_zero[Bc * Hc];
__device__ int   g_tok[Bc];
__device__ float g_SK[3 * KSPLIT * BCHC];      // split-K partial sums (24 MB)

// ---------------- packed fp32 helpers (sm_103a f32x2) ----------------
__device__ __forceinline__ ull dup2(float a) {
    ull r;
    asm("mov.b64 %0, {%1, %1};" : "=l"(r) : "r"(__float_as_uint(a)));
    return r;
}
__device__ __forceinline__ void ffma2(ull& d, ull a, ull b) {
    asm("fma.rn.f32x2 %0, %1, %2, %0;" : "+l"(d) : "l"(a), "l"(b));
}
__device__ __forceinline__ void unpk(ull v, float& lo, float& hi) {
    unsigned int a, b;
    asm("mov.b64 {%0, %1}, %2;" : "=r"(a), "=r"(b) : "l"(v));
    lo = __uint_as_float(a);
    hi = __uint_as_float(b);
}

// ---------------- job descriptors ----------------
struct GemmJob {
    const float* A; long lda; const float* W;  // C/part = A @ W^T (+ epilogue)
    int K;
    const int* gather;                          // optional row gather on A
    const float* bias; const float* addmat; long ldadd;
    float* C; long ldc;                         // direct mode output
    float* part;                                // split-K partial base (slot)
    int act; int valid;
};
struct EpiJob {
    const float* part;                          // KSPLIT partials, stride BCHC
    const float* bias; const float* addmat; long ldadd;
    float* C; long ldc; int act; int valid;
};

// ---------------- tile loaders (BR rows x 16 k-cols) ----------------
template<int NT, int BR>
__device__ __forceinline__ void load_tile(
    const float* __restrict__ A, long lda, const int* __restrict__ gather,
    int r_base, int K, int k0, int tid, float (&r)[BR * 4 / NT][4])
{
    constexpr int NC = BR * 4 / NT;
#pragma unroll
    for (int i = 0; i < NC; i++) {
        int cid = tid + i * NT;
        int row = cid >> 2, kq = cid & 3;
        int kk = k0 + kq * 4;
        long arow = gather ? (long)__ldg(&gather[r_base + row]) : (long)(r_base + row);
        const float* p = A + arow * lda + kk;
        if (kk + 3 < K && ((((uintptr_t)p) & 15u) == 0)) {
            float4 v = *(const float4*)p;
            r[i][0] = v.x; r[i][1] = v.y; r[i][2] = v.z; r[i][3] = v.w;
        } else {
#pragma unroll
            for (int j = 0; j < 4; j++)
                r[i][j] = (kk + j < K) ? __ldg(p + j) : 0.0f;
        }
    }
}

template<int NT, int BR>
__device__ __forceinline__ void store_tile(
    float (&S)[16][BR], int tid, const float (&r)[BR * 4 / NT][4])
{
    constexpr int NC = BR * 4 / NT;
#pragma unroll
    for (int i = 0; i < NC; i++) {
        int cid = tid + i * NT;
        int row = cid >> 2, kq = cid & 3;
#pragma unroll
        for (int j = 0; j < 4; j++)
            S[kq * 4 + j][row] = r[i][j];
    }
}

// ---------------- micro-kernel: TM x TN per thread via f32x2 ----------------
// TM=8 cuts issue slots/MAC: 27 issues per 1024 warp-MACs (vs 18 per 512 at TM=4)
template<int BM, int BN, int TM, int TN>
__device__ __forceinline__ void mac_block(
    const float (&As)[16][BM], const float (&Ws)[16][BN],
    int r0, int c0, ull (&acc)[TM][TN / 2])
{
#pragma unroll
    for (int k = 0; k < 16; k++) {
        ull ad[TM];
#pragma unroll
        for (int i = 0; i < TM; i += 4) {
            float4 av = *(const float4*)&As[k][r0 + i];
            ad[i + 0] = dup2(av.x);
            ad[i + 1] = dup2(av.y);
            ad[i + 2] = dup2(av.z);
            ad[i + 3] = dup2(av.w);
        }
        ull wv[TN / 2];
#pragma unroll
        for (int p = 0; p < TN / 2; p += 2) {
            ulonglong2 w2 = *(const ulonglong2*)&Ws[k][c0 + 2 * p];
            wv[p] = w2.x;
            wv[p + 1] = w2.y;
        }
#pragma unroll
        for (int i = 0; i < TM; i++)
#pragma unroll
            for (int p = 0; p < TN / 2; p++)
                ffma2(acc[i][p], ad[i], wv[p]);
    }
}

// ---------------- K-staged double-buffered mainloop ----------------
// Kloop = #columns to process; lda_w = W row stride (full K for split mode)
template<int NT, int BM, int BN, int TM, int TN>
__device__ __forceinline__ void gemm_mainloop(
    const float* __restrict__ A, long lda,
    const float* __restrict__ W, long lda_w, int Kloop,
    const int* __restrict__ gather,
    int m0, int n0, int tid, int r0, int c0,
    float (&As)[2][16][BM], float (&Ws)[2][16][BN],
    ull (&acc)[TM][TN / 2])
{
    constexpr int NCA = BM * 4 / NT;
    constexpr int NCW = BN * 4 / NT;
    float ar[NCA][4], wr[NCW][4];
    int nkb = (Kloop + 15) / 16;

    load_tile<NT, BM>(A, lda, gather, m0, Kloop, 0, tid, ar);
    load_tile<NT, BN>(W, lda_w, nullptr, n0, Kloop, 0, tid, wr);
    store_tile<NT, BM>(As[0], tid, ar);
    store_tile<NT, BN>(Ws[0], tid, wr);
    __syncthreads();

    int buf = 0;
    for (int kb = 0; kb < nkb; kb++) {
        bool hn = (kb + 1 < nkb);
        if (hn) {
            load_tile<NT, BM>(A, lda, gather, m0, Kloop, (kb + 1) * 16, tid, ar);
            load_tile<NT, BN>(W, lda_w, nullptr, n0, Kloop, (kb + 1) * 16, tid, wr);
        }
        mac_block<BM, BN, TM, TN>(As[buf], Ws[buf], r0, c0, acc);
        if (hn) {
            store_tile<NT, BM>(As[buf ^ 1], tid, ar);
            store_tile<NT, BN>(Ws[buf ^ 1], tid, wr);
        }
        __syncthreads();
        buf ^= 1;
    }
}

// ---------------- direct GEMM kernel (precompute path) ----------------
template<int NT, int BM, int BN, int TM, int TN>
__global__ void __launch_bounds__(NT)
gemm3_kernel(GemmJob j0, GemmJob j1, GemmJob j2)
{
    GemmJob j = (blockIdx.z == 0) ? j0 : ((blockIdx.z == 1) ? j1 : j2);
    if (!j.valid) return;

    __shared__ float As[2][16][BM];
    __shared__ float Ws[2][16][BN];

    constexpr int CT = BN / TN;
    int tid = threadIdx.x;
    int m0 = blockIdx.y * BM;
    int n0 = blockIdx.x * BN;
    int ty = tid / CT, tx = tid % CT;
    int r0 = ty * TM, c0 = tx * TN;

    ull acc[TM][TN / 2] = {};
    gemm_mainloop<NT, BM, BN, TM, TN>(j.A, j.lda, j.W, (long)j.K, j.K, j.gather,
                                      m0, n0, tid, r0, c0, As, Ws, acc);

#pragma unroll
    for (int i = 0; i < TM; i++) {
        int m = m0 + r0 + i;
        float o[TN];
#pragma unroll
        for (int p = 0; p < TN / 2; p++)
            unpk(acc[i][p], o[2 * p], o[2 * p + 1]);
#pragma unroll
        for (int q = 0; q < TN; q++) {
            float v = o[q];
            int n = n0 + c0 + q;
            if (j.bias)   v += __ldg(&j.bias[n]);
            if (j.addmat) v += __ldg(&j.addmat[(long)m * j.ldadd + n]);
            if (j.act)    v = tanhf(v);
            o[q] = v;
        }
#pragma unroll
        for (int q = 0; q < TN; q += 4)
            *(float4*)&j.C[(long)m * j.ldc + n0 + c0 + q] = *(const float4*)&o[q];
    }
}

// ---------------- split-K GEMM kernel: raw partial sums to scratch ----------------
// blockIdx.z = job * KSPLIT + h; block computes columns [h*K/KS, (h+1)*K/KS)
template<int NT, int BM, int BN, int TM, int TN>
__global__ void __launch_bounds__(NT)
gemmsk_kernel(GemmJob j0, GemmJob j1, GemmJob j2)
{
    int job = blockIdx.z / KSPLIT;
    int h = blockIdx.z % KSPLIT;
    GemmJob j = (job == 0) ? j0 : ((job == 1) ? j1 : j2);
    if (!j.valid) return;

    __shared__ float As[2][16][BM];
    __shared__ float Ws[2][16][BN];

    constexpr int CT = BN / TN;
    int tid = threadIdx.x;
    int m0 = blockIdx.y * BM;
    int n0 = blockIdx.x * BN;
    int ty = tid / CT, tx = tid % CT;
    int r0 = ty * TM, c0 = tx * TN;

    int Kh = j.K / KSPLIT;
    const float* A = j.A + (long)h * Kh;   // column offset; rows via lda
    const float* W = j.W + (long)h * Kh;

    ull acc[TM][TN / 2] = {};
    gemm_mainloop<NT, BM, BN, TM, TN>(A, j.lda, W, (long)j.K, Kh, j.gather,
                                      m0, n0, tid, r0, c0, As, Ws, acc);

    float* P = j.part + (size_t)h * BCHC;
#pragma unroll
    for (int i = 0; i < TM; i++) {
        int m = m0 + r0 + i;
        float o[TN];
#pragma unroll
        for (int p = 0; p < TN / 2; p++)
            unpk(acc[i][p], o[2 * p], o[2 * p + 1]);
#pragma unroll
        for (int q = 0; q < TN; q += 4)
            *(float4*)&P[(size_t)m * Hc + n0 + c0 + q] = *(const float4*)&o[q];
    }
}

// ---------------- epilogue value: sum KSPLIT parts + bias + addmat (+tanh) ----------------
__device__ __forceinline__ float4 epi_value(const EpiJob& e, size_t idx, int m, int n)
{
    float4 s = *(const float4*)&e.part[idx];
#pragma unroll
    for (int h = 1; h < KSPLIT; h++) {
        float4 p = *(const float4*)&e.part[(size_t)h * BCHC + idx];
        s.x += p.x; s.y += p.y; s.z += p.z; s.w += p.w;
    }
    if (e.bias) {
        float4 b = *(const float4*)&e.bias[n];
        s.x += b.x; s.y += b.y; s.z += b.z; s.w += b.w;
    }
    if (e.addmat) {
        float4 a = *(const float4*)&e.addmat[(long)m * e.ldadd + n];
        s.x += a.x; s.y += a.y; s.z += a.z; s.w += a.w;
    }
    if (e.act) {
        s.x = tanhf(s.x); s.y = tanhf(s.y); s.z = tanhf(s.z); s.w = tanhf(s.w);
    }
    return s;
}

// ---------------- split-K epilogue (up to 3 jobs) ----------------
__global__ void __launch_bounds__(256)
epi_kernel(EpiJob e0, EpiJob e1, EpiJob e2)
{
    EpiJob e = (blockIdx.y == 0) ? e0 : ((blockIdx.y == 1) ? e1 : e2);
    if (!e.valid) return;

    size_t idx = ((size_t)blockIdx.x * 256 + threadIdx.x) * 4;
    int m = (int)(idx >> 10);          // / Hc
    int n = (int)(idx & (Hc - 1));     // % Hc
    float4 s = epi_value(e, idx, m, n);
    *(float4*)&e.C[(long)m * e.ldc + n] = s;
}

// ---------------- decoder L2 epilogue FUSED with logits+argmax ----------------
// blockIdx.y == 0: job d1 -- one block = one batch row b; after writing d1,
//                  compute logits[b,:] and tok[b] in the same block.
// blockIdx.y == 1: job P0 (plain epilogue).
__global__ void __launch_bounds__(256)
epi_logits_kernel(EpiJob e0, EpiJob e1,
                  const float* __restrict__ fcW, const float* __restrict__ fcb,
                  float* __restrict__ out, int step, int* __restrict__ tok)
{
    __shared__ float hs[Hc];
    __shared__ float vals[Vc];

    EpiJob e = (blockIdx.y == 0) ? e0 : e1;
    int b = blockIdx.x, tid = threadIdx.x;
    size_t idx = ((size_t)b << 10) + (size_t)tid * 4;   // row b, cols tid*4..
    int n = tid * 4;

    float4 s = epi_value(e, idx, b, n);
    *(float4*)&e.C[(long)b * e.ldc + n] = s;

    if (blockIdx.y != 0) return;

    // logits tail: hs = d1[b,:]
    *(float4*)&hs[n] = s;
    __syncthreads();

    int warp = tid >> 5, lane = tid & 31;
#pragma unroll
    for (int j = 0; j < 8; j++) {
        int v = warp * 8 + j;
        const float4* wp = (const float4*)&fcW[(size_t)v * Hc];
        float sum = 0.0f;
#pragma unroll
        for (int i = 0; i < 8; i++) {
            float4 w4 = __ldg(&wp[lane + i * 32]);
            float4 h4 = *(const float4*)&hs[(lane + i * 32) * 4];
            sum += w4.x * h4.x + w4.y * h4.y + w4.z * h4.z + w4.w * h4.w;
        }
#pragma unroll
        for (int o = 16; o; o >>= 1) sum += __shfl_xor_sync(0xffffffffu, sum, o);
        if (lane == 0) {
            sum += fcb[v];
            vals[v] = sum;
            out[((size_t)b * Vc + (size_t)v) * ML + (size_t)step] = sum;
        }
    }
    __syncthreads();
    if (tid == 0) {
        float best = vals[0]; int bi = 0;
#pragma unroll
        for (int i = 1; i < Vc; i++)
            if (vals[i] > best) { best = vals[i]; bi = i; }   // first-max = jnp.argmax
        tok[b] = bi;
    }
}

__global__ void init_kernel(float* __restrict__ z, int* __restrict__ tok)
{
    int i = blockIdx.x * blockDim.x + threadIdx.x;
    if (i < Bc * Hc) z[i] = 0.0f;
    if (i < Bc) tok[i] = 0;
}

__global__ void copy_hidden_kernel(const float* __restrict__ d0,
                                   const float* __restrict__ d1,
                                   float* __restrict__ o)
{
    int i = blockIdx.x * blockDim.x + threadIdx.x;
    if (i < Bc * Hc) {
        o[i] = d0[i];
        o[Bc * Hc + i] = d1[i];
    }
}

// ---------------- host ----------------
extern "C" void kernel_launch(void* const* d_in, const int* in_sizes, int n_in,
                              void* d_out, int out_size)
{
    (void)in_sizes; (void)n_in; (void)out_size;
    const float* x     = (const float*)d_in[0];
    const float* emb   = (const float*)d_in[1];
    const float* eWih0 = (const float*)d_in[2];
    const float* eWhh0 = (const float*)d_in[3];
    const float* eb0   = (const float*)d_in[4];
    const float* eWih1 = (const float*)d_in[5];
    const float* eWhh1 = (const float*)d_in[6];
    const float* eb1   = (const float*)d_in[7];
    const float* dWih0 = (const float*)d_in[8];
    const float* dWhh0 = (const float*)d_in[9];
    const float* db0   = (const float*)d_in[10];
    const float* dWih1 = (const float*)d_in[11];
    const float* dWhh1 = (const float*)d_in[12];
    const float* db1   = (const float*)d_in[13];
    const float* fcW   = (const float*)d_in[14];
    const float* fcb   = (const float*)d_in[15];
    float* out = (float*)d_out;

    float *U0, *h0base, *h1base, *Vbase, *d0base, *d1base, *P0, *P1, *zero, *SK;
    int* tok;
    cudaGetSymbolAddress((void**)&U0, g_U0);
    cudaGetSymbolAddress((void**)&h0base, g_h0);
    cudaGetSymbolAddress((void**)&h1base, g_h1);
    cudaGetSymbolAddress((void**)&Vbase, g_V);
    cudaGetSymbolAddress((void**)&d0base, g_d0);
    cudaGetSymbolAddress((void**)&d1base, g_d1);
    cudaGetSymbolAddress((void**)&P0, g_P0);
    cudaGetSymbolAddress((void**)&P1, g_P1);
    cudaGetSymbolAddress((void**)&zero, g_zero);
    cudaGetSymbolAddress((void**)&tok, g_tok);
    cudaGetSymbolAddress((void**)&SK, g_SK);

    float* h0b[2] = { h0base, h0base + BCHC };
    float* h1b[2] = { h1base, h1base + BCHC };
    float* Vb[2]  = { Vbase,  Vbase  + BCHC };
    float* d0b[2] = { d0base, d0base + BCHC };
    float* d1b[2] = { d1base, d1base + BCHC };
    float* SKs[3] = { SK, SK + KSPLIT * BCHC, SK + 2 * KSPLIT * BCHC };

    init_kernel<<<(Bc * Hc + 255) / 256, 256>>>(zero, tok);

    GemmJob inv = {}; inv.valid = 0;
    EpiJob einv = {}; einv.valid = 0;

    // ---- precompute U0 = x_flat @ eWih0^T + b0 (direct path) ----
    {
        GemmJob j = {};
        j.A = x; j.lda = Lc; j.W = eWih0; j.K = Lc;
        j.bias = eb0;
        j.C = U0; j.ldc = Hc; j.act = 0; j.valid = 1;
        gemm3_kernel<256, 128, 64, 8, 4>
            <<<dim3(Hc / 64, (Bc * Tc) / 128, 1), 256>>>(j, inv, inv);
    }

    dim3 grid_epi3(Bc, 3);   // one block = one (job, batch-row)

    // ---- encoder: 3 balanced split-K units per launch (skewed chain) ----
    // TM=8 / 64x128 tiles: 27 issue slots per 1024 warp-MACs (issue-cap x1.33)
    // launch t: A) h0_t = tanh(h0_{t-1}@Whh0 + U0[:,t])
    //           B) V_{t-1} = h0_{t-1}@Wih1 + b1
    //           C) h1_{t-2} = tanh(h1_{t-3}@Whh1 + V_{t-2})
    // t == Tc: slot A computes decoder bootstrap P0 = h0_final @ dWhh0
    for (int t = 0; t <= Tc + 1; t++) {
        GemmJob jA = inv, jB = inv, jC = inv;
        EpiJob eA = einv, eB = einv, eC = einv;
        if (t < Tc) {
            jA.A = (t == 0) ? zero : h0b[(t - 1) & 1];
            jA.lda = Hc; jA.W = eWhh0; jA.K = Hc;
            jA.part = SKs[0]; jA.valid = 1;
            eA.part = SKs[0]; eA.addmat = U0 + (size_t)t * Hc; eA.ldadd = (long)Tc * Hc;
            eA.C = h0b[t & 1]; eA.ldc = Hc; eA.act = 1; eA.valid = 1;
        } else if (t == Tc) {
            jA.A = h0b[(Tc - 1) & 1]; jA.lda = Hc; jA.W = dWhh0; jA.K = Hc;
            jA.part = SKs[0]; jA.valid = 1;
            eA.part = SKs[0]; eA.C = P0; eA.ldc = Hc; eA.act = 0; eA.valid = 1;
        }
        if (t >= 1 && t <= Tc) {
            int s = t - 1;
            jB.A = h0b[s & 1]; jB.lda = Hc; jB.W = eWih1; jB.K = Hc;
            jB.part = SKs[1]; jB.valid = 1;
            eB.part = SKs[1]; eB.bias = eb1;
            eB.C = Vb[s & 1]; eB.ldc = Hc; eB.act = 0; eB.valid = 1;
        }
        if (t >= 2) {
            int s = t - 2;
            jC.A = (s == 0) ? zero : h1b[(s - 1) & 1];
            jC.lda = Hc; jC.W = eWhh1; jC.K = Hc;
            jC.part = SKs[2]; jC.valid = 1;
            eC.part = SKs[2]; eC.addmat = Vb[s & 1]; eC.ldadd = Hc;
            eC.C = h1b[s & 1]; eC.ldc = Hc; eC.act = 1; eC.valid = 1;
        }
        gemmsk_kernel<256, 64, 128, 8, 4>
            <<<dim3(Hc / 128, Bc / 64, 3 * KSPLIT), 256>>>(jA, jB, jC);
        epi_kernel<<<grid_epi3, 256>>>(eA, eB, eC);
    }

    // ---- decoder: 2 balanced split-K units per GEMM launch (P0/P1 pre-rotation) ----
    const float* d1prev = h1b[(Tc - 1) & 1];
    for (int s = 0; s < ML; s++) {
        float* d0cur = d0b[s & 1];
        float* d1cur = d1b[s & 1];
        {   // L1: d0_s = tanh(emb[tok]@Wih0 + P0 + b0);  P1 = d1_{s-1}@Whh1
            GemmJob jA = inv, jB = inv;
            EpiJob eA = einv, eB = einv;
            jA.A = emb; jA.lda = Hc; jA.W = dWih0; jA.K = Hc;
            jA.gather = tok; jA.part = SKs[0]; jA.valid = 1;
            eA.part = SKs[0]; eA.bias = db0; eA.addmat = P0; eA.ldadd = Hc;
            eA.C = d0cur; eA.ldc = Hc; eA.act = 1; eA.valid = 1;
            jB.A = d1prev; jB.lda = Hc; jB.W = dWhh1; jB.K = Hc;
            jB.part = SKs[1]; jB.valid = 1;
            eB.part = SKs[1]; eB.C = P1; eB.ldc = Hc; eB.act = 0; eB.valid = 1;
            gemmsk_kernel<256, 64, 128, 8, 4>
                <<<dim3(Hc / 128, Bc / 64, 2 * KSPLIT), 256>>>(jA, jB, inv);
            epi_kernel<<<dim3(Bc, 2), 256>>>(eA, eB, einv);
        }
        {   // L2: d1_s = tanh(d0_s@Wih1 + P1 + b1)  [+ fused logits/argmax];
            // P0 = d0_s@Whh0 (for s+1)
            GemmJob jA = inv, jB = inv;
            EpiJob eA = einv, eB = einv;
            jA.A = d0cur; jA.lda = Hc; jA.W = dWih1; jA.K = Hc;
            jA.part = SKs[0]; jA.valid = 1;
            eA.part = SKs[0]; eA.bias = db1; eA.addmat = P1; eA.ldadd = Hc;
            eA.C = d1cur; eA.ldc = Hc; eA.act = 1; eA.valid = 1;
            jB.A = d0cur; jB.lda = Hc; jB.W = dWhh0; jB.K = Hc;
            jB.part = SKs[1]; jB.valid = 1;
            eB.part = SKs[1]; eB.C = P0; eB.ldc = Hc; eB.act = 0; eB.valid = 1;
            gemmsk_kernel<256, 64, 128, 8, 4>
                <<<dim3(Hc / 128, Bc / 64, 2 * KSPLIT), 256>>>(jA, jB, inv);
            epi_logits_kernel<<<dim3(Bc, 2), 256>>>(eA, eB, fcW, fcb, out, s, tok);
        }
        d1prev = d1b[s & 1];
    }

    copy_hidden_kernel<<<(Bc * Hc + 255) / 256, 256>>>(
        d0b[(ML - 1) & 1], d1b[(ML - 1) & 1], out + (size_t)Bc * Vc * ML);
}